// round 10
// baseline (speedup 1.0000x reference)
#include <cuda_runtime.h>
#include <math.h>
#include <float.h>
#include <stdint.h>

#define BATCH   2
#define SEQ     2048
#define DMODEL  1024
#define NHEADS  16
#define HDIM    64
#define MROWS   (BATCH*SEQ)     // 4096
#define QKVN    (3*DMODEL)      // 3072
#define BHT     (BATCH*NHEADS)  // 32

// ---------------- scratch (device globals; no allocations allowed) ----------
static __device__ float g_qkv[(size_t)MROWS * QKVN];
static __device__ float g_q  [(size_t)BHT * SEQ * HDIM];
static __device__ float g_k  [(size_t)BHT * SEQ * HDIM];
static __device__ float g_v  [(size_t)BHT * SEQ * HDIM];
static __device__ float g_o  [(size_t)BHT * SEQ * HDIM];

// ---------------- helpers ----------------
__device__ __forceinline__ uint32_t f2tf(float f) {
    uint32_t u;
    asm("cvt.rna.tf32.f32 %0, %1;" : "=r"(u) : "f"(f));
    return u;
}

__device__ __forceinline__ uint32_t smem_u32(const void* p) {
    uint32_t a;
    asm("{ .reg .u64 t; cvta.to.shared.u64 t, %1; cvt.u32.u64 %0, t; }" : "=r"(a) : "l"(p));
    return a;
}

__device__ __forceinline__ void cp_async16(uint32_t dst, const void* src) {
    asm volatile("cp.async.ca.shared.global [%0], [%1], 16;" :: "r"(dst), "l"(src) : "memory");
}
#define CP_COMMIT() asm volatile("cp.async.commit_group;" ::: "memory")
#define CP_WAIT(n)  asm volatile("cp.async.wait_group %0;" :: "n"(n) : "memory")

// D = A(16x8) * B(8x8) + D, tf32 in / fp32 out  (legacy tensor pipe)
__device__ __forceinline__ void mma8(float* d, const uint32_t* a, uint32_t b0, uint32_t b1) {
    asm volatile(
        "mma.sync.aligned.m16n8k8.row.col.f32.tf32.tf32.f32 "
        "{%0,%1,%2,%3}, {%4,%5,%6,%7}, {%8,%9}, {%0,%1,%2,%3};"
        : "+f"(d[0]), "+f"(d[1]), "+f"(d[2]), "+f"(d[3])
        : "r"(a[0]), "r"(a[1]), "r"(a[2]), "r"(a[3]), "r"(b0), "r"(b1));
}

// ============ TF32 mma.sync GEMM with 4-stage cp.async pipeline =============
// C[M,N] = A[M,K] * B[N,K]^T + bias[N]. 128x128 CTA tile, k16 stages.
// 256 threads = 8 warps (2m x 4n), warp tile 64x32.
// SMEM stores raw fp32 (pad GP=20 -> conflict-free STS and frag LDS);
// cvt.rna.tf32 happens at fragment load.
// GATHER: A rows are read from g_o's [B,H,S,Hd] layout (fused head gather);
// a k16 block never crosses a 64-wide head boundary, so offsets stay simple.
#define GP      20
#define STAGES  4
#define G_TILE  (128 * GP)                       // floats per operand stage
#define GEMM_SMEM (2 * STAGES * G_TILE * 4)      // 81920 bytes

template<bool GATHER>
__global__ __launch_bounds__(256)
void gemm_tf32_pipe(const float* __restrict__ A, const float* __restrict__ B,
                    const float* __restrict__ bias, float* __restrict__ C,
                    int M, int N, int K)
{
    extern __shared__ float sm_f[];
    float* AsBase = sm_f;                        // [STAGES][G_TILE]
    float* BsBase = sm_f + STAGES * G_TILE;

    const int tid  = threadIdx.x;
    const int warp = tid >> 5, lane = tid & 31;
    const int g    = lane >> 2, tig = lane & 3;
    const int wm   = (warp >> 2) * 64;
    const int wn   = (warp & 3) * 32;
    const int bm   = blockIdx.y * 128;
    const int bn   = blockIdx.x * 128;

    // producer mapping: 8 consecutive lanes = 8 consecutive rows, same kc
    // (bank-stride 20 -> conflict-free STS phases)
    const int kc = ((tid >> 3) & 3) << 2;          // 0,4,8,12
    const int r0 = (tid & 7) + ((tid >> 5) << 3);  // 0..63

    float acc[4][4][4];
#pragma unroll
    for (int mt = 0; mt < 4; mt++)
#pragma unroll
        for (int nt = 0; nt < 4; nt++)
#pragma unroll
            for (int j = 0; j < 4; j++) acc[mt][nt][j] = 0.f;

    // A-row source pointer (optionally head-gathered from [B,H,S,Hd])
    auto a_src = [&](int row, int kcol) -> const float* {
        if (!GATHER) {
            return A + (size_t)(bm + row) * K + kcol;
        } else {
            int m = bm + row;
            int b = m >> 11, s = m & 2047;
            int h = kcol >> 6, hd = kcol & 63;
            return A + ((((size_t)(b * NHEADS + h) << 11) + s) << 6) + hd;
        }
    };

    auto issue = [&](int ch) {
        const int st = ch & (STAGES - 1);
        const int k0 = ch << 4;
        float* as = AsBase + st * G_TILE;
        float* bs = BsBase + st * G_TILE;
#pragma unroll
        for (int p = 0; p < 2; p++) {
            int row = r0 + (p << 6);
            cp_async16(smem_u32(as + row * GP + kc), a_src(row, k0 + kc));
            cp_async16(smem_u32(bs + row * GP + kc),
                       B + (size_t)(bn + row) * K + k0 + kc);
        }
        CP_COMMIT();
    };

    const int nch = K >> 4;   // 64
    issue(0); issue(1); issue(2);

    for (int ch = 0; ch < nch; ch++) {
        CP_WAIT(2);           // chunk ch's group complete (this thread)
        __syncthreads();      // block-wide visibility; also frees stage ch-1
        const float* as = AsBase + (ch & (STAGES - 1)) * G_TILE;
        const float* bs = BsBase + (ch & (STAGES - 1)) * G_TILE;

#pragma unroll
        for (int ks = 0; ks < 16; ks += 8) {
            uint32_t af[4][4];
#pragma unroll
            for (int mt = 0; mt < 4; mt++) {
                int m0 = wm + mt * 16 + g;
                af[mt][0] = f2tf(as[m0 * GP + ks + tig]);
                af[mt][1] = f2tf(as[(m0 + 8) * GP + ks + tig]);
                af[mt][2] = f2tf(as[m0 * GP + ks + tig + 4]);
                af[mt][3] = f2tf(as[(m0 + 8) * GP + ks + tig + 4]);
            }
#pragma unroll
            for (int nt = 0; nt < 4; nt++) {
                int n0 = wn + nt * 8 + g;
                uint32_t b0 = f2tf(bs[n0 * GP + ks + tig]);
                uint32_t b1 = f2tf(bs[n0 * GP + ks + tig + 4]);
#pragma unroll
                for (int mt = 0; mt < 4; mt++)
                    mma8(acc[mt][nt], af[mt], b0, b1);
            }
        }
        if (ch + 3 < nch) issue(ch + 3);
    }

#pragma unroll
    for (int nt = 0; nt < 4; nt++) {
        int cc = bn + wn + nt * 8 + 2 * tig;
        float bv0 = bias[cc], bv1 = bias[cc + 1];
#pragma unroll
        for (int mt = 0; mt < 4; mt++) {
            int rr = bm + wm + mt * 16 + g;
            float2 v0, v1;
            v0.x = acc[mt][nt][0] + bv0; v0.y = acc[mt][nt][1] + bv1;
            v1.x = acc[mt][nt][2] + bv0; v1.y = acc[mt][nt][3] + bv1;
            *reinterpret_cast<float2*>(C + (size_t)rr * N + cc)       = v0;
            *reinterpret_cast<float2*>(C + (size_t)(rr + 8) * N + cc) = v1;
        }
    }
}

// ---------------- RoPE + split qkv[M,3*D] -> q/k/v [B,H,S,Hd] ----------------
__global__ void rope_split_kernel(const float* __restrict__ qkv,
                                  float* __restrict__ q, float* __restrict__ k,
                                  float* __restrict__ v)
{
    int idx = blockIdx.x * blockDim.x + threadIdx.x;
    if (idx >= MROWS * NHEADS * (HDIM / 2)) return;
    int j = idx & 31;
    int h = (idx >> 5) & 15;
    int m = idx >> 9;
    int b = m >> 11;
    int s = m & 2047;

    float inv_freq = 1.0f / powf(10000.0f, (float)j * (1.0f / 32.0f));
    float ang = (float)s * inv_freq;
    float sn, c;
    sincosf(ang, &sn, &c);

    size_t ib = (size_t)m * QKVN + (size_t)h * HDIM;
    size_t ob = ((size_t)(b * NHEADS + h) * SEQ + s) * HDIM;

    float q1 = qkv[ib + j],          q2 = qkv[ib + 32 + j];
    q[ob + j]      = q1 * c  - q2 * sn;
    q[ob + 32 + j] = q1 * sn + q2 * c;

    float k1 = qkv[ib + DMODEL + j], k2 = qkv[ib + DMODEL + 32 + j];
    k[ob + j]      = k1 * c  - k2 * sn;
    k[ob + 32 + j] = k1 * sn + k2 * c;

    v[ob + j]      = qkv[ib + 2 * DMODEL + j];
    v[ob + 32 + j] = qkv[ib + 2 * DMODEL + 32 + j];
}

// ============ TF32 mma.sync causal flash attention (proven, unchanged) ======
#define AP 68
#define ATTN_SMEM ((128 + 64 + 64 + 128) * AP * 4)
__global__ __launch_bounds__(256)
void attn_tc_kernel(const float* __restrict__ Q, const float* __restrict__ K,
                    const float* __restrict__ V, float* __restrict__ O)
{
    extern __shared__ uint32_t sm_u[];
    uint32_t* Qs = sm_u;
    uint32_t* Ks = Qs + 128 * AP;
    uint32_t* Vt = Ks + 64 * AP;
    uint32_t* Ps = Vt + 64 * AP;

    const int tid  = threadIdx.x;
    const int warp = tid >> 5, lane = tid & 31;
    const int g    = lane >> 2, tig = lane & 3;
    const int wm   = warp * 16;
    const int bh   = blockIdx.y;
    const int qi   = gridDim.x - 1 - blockIdx.x;
    const int q0   = qi * 128;

    const float* Qb = Q + (size_t)bh * SEQ * HDIM;
    const float* Kb = K + (size_t)bh * SEQ * HDIM;
    const float* Vb = V + (size_t)bh * SEQ * HDIM;

#pragma unroll
    for (int p = 0; p < 8; p++) {
        int idx = tid + p * 256;
        int row = idx >> 4, c4 = (idx & 15) << 2;
        float4 val = *reinterpret_cast<const float4*>(Qb + (size_t)(q0 + row) * HDIM + c4);
        uint4 u;
        u.x = f2tf(val.x); u.y = f2tf(val.y); u.z = f2tf(val.z); u.w = f2tf(val.w);
        *reinterpret_cast<uint4*>(&Qs[row * AP + c4]) = u;
    }

    float oacc[8][4];
#pragma unroll
    for (int nt = 0; nt < 8; nt++)
#pragma unroll
        for (int j = 0; j < 4; j++) oacc[nt][j] = 0.f;
    float m0 = -1e30f, m1 = -1e30f, l0 = 0.f, l1 = 0.f;

    const int vk = tid & 63;
    const int vd = (tid >> 6) << 2;
    const int rg0 = q0 + wm + g;
    const int rg1 = rg0 + 8;

    const int nkt = (q0 >> 6) + 2;
    for (int kt = 0; kt < nkt; kt++) {
        const int kg = kt << 6;
        __syncthreads();
#pragma unroll
        for (int p = 0; p < 4; p++) {
            int idx = tid + p * 256;
            int row = idx >> 4, c4 = (idx & 15) << 2;
            float4 kv = *reinterpret_cast<const float4*>(Kb + (size_t)(kg + row) * HDIM + c4);
            uint4 u;
            u.x = f2tf(kv.x); u.y = f2tf(kv.y); u.z = f2tf(kv.z); u.w = f2tf(kv.w);
            *reinterpret_cast<uint4*>(&Ks[row * AP + c4]) = u;
        }
#pragma unroll
        for (int p = 0; p < 4; p++) {
            int d4 = vd + p * 16;
            float4 vv = *reinterpret_cast<const float4*>(Vb + (size_t)(kg + vk) * HDIM + d4);
            Vt[(d4 + 0) * AP + vk] = f2tf(vv.x);
            Vt[(d4 + 1) * AP + vk] = f2tf(vv.y);
            Vt[(d4 + 2) * AP + vk] = f2tf(vv.z);
            Vt[(d4 + 3) * AP + vk] = f2tf(vv.w);
        }
        __syncthreads();

        float sacc[8][4];
#pragma unroll
        for (int nt = 0; nt < 8; nt++)
#pragma unroll
            for (int j = 0; j < 4; j++) sacc[nt][j] = 0.f;
#pragma unroll
        for (int ks = 0; ks < 64; ks += 8) {
            uint32_t a[4];
            a[0] = Qs[(wm + g) * AP + ks + tig];
            a[1] = Qs[(wm + g + 8) * AP + ks + tig];
            a[2] = Qs[(wm + g) * AP + ks + tig + 4];
            a[3] = Qs[(wm + g + 8) * AP + ks + tig + 4];
#pragma unroll
            for (int nt = 0; nt < 8; nt++) {
                uint32_t b0 = Ks[(nt * 8 + g) * AP + ks + tig];
                uint32_t b1 = Ks[(nt * 8 + g) * AP + ks + tig + 4];
                mma8(sacc[nt], a, b0, b1);
            }
        }
        const bool need_mask = (kg + 63) > rg0;
#pragma unroll
        for (int nt = 0; nt < 8; nt++) {
#pragma unroll
            for (int j = 0; j < 4; j++) sacc[nt][j] *= 0.125f;
            if (need_mask) {
                int cg = kg + nt * 8 + 2 * tig;
                if (cg     > rg0) sacc[nt][0] = -1e30f;
                if (cg + 1 > rg0) sacc[nt][1] = -1e30f;
                if (cg     > rg1) sacc[nt][2] = -1e30f;
                if (cg + 1 > rg1) sacc[nt][3] = -1e30f;
            }
        }

        float rmax0 = -1e30f, rmax1 = -1e30f;
#pragma unroll
        for (int nt = 0; nt < 8; nt++) {
            rmax0 = fmaxf(rmax0, fmaxf(sacc[nt][0], sacc[nt][1]));
            rmax1 = fmaxf(rmax1, fmaxf(sacc[nt][2], sacc[nt][3]));
        }
        rmax0 = fmaxf(rmax0, __shfl_xor_sync(0xffffffffu, rmax0, 1));
        rmax0 = fmaxf(rmax0, __shfl_xor_sync(0xffffffffu, rmax0, 2));
        rmax1 = fmaxf(rmax1, __shfl_xor_sync(0xffffffffu, rmax1, 1));
        rmax1 = fmaxf(rmax1, __shfl_xor_sync(0xffffffffu, rmax1, 2));

        float mn0 = fmaxf(m0, rmax0), mn1 = fmaxf(m1, rmax1);
        float al0 = __expf(m0 - mn0), al1 = __expf(m1 - mn1);
        m0 = mn0; m1 = mn1;

        float rs0 = 0.f, rs1 = 0.f;
#pragma unroll
        for (int nt = 0; nt < 8; nt++) {
            float p0 = __expf(sacc[nt][0] - mn0);
            float p1 = __expf(sacc[nt][1] - mn0);
            float p2 = __expf(sacc[nt][2] - mn1);
            float p3 = __expf(sacc[nt][3] - mn1);
            rs0 += p0 + p1; rs1 += p2 + p3;
            int col = nt * 8 + 2 * tig;
            uint2 u01, u23;
            u01.x = f2tf(p0); u01.y = f2tf(p1);
            u23.x = f2tf(p2); u23.y = f2tf(p3);
            *reinterpret_cast<uint2*>(&Ps[(wm + g) * AP + col])     = u01;
            *reinterpret_cast<uint2*>(&Ps[(wm + g + 8) * AP + col]) = u23;
        }
        rs0 += __shfl_xor_sync(0xffffffffu, rs0, 1);
        rs0 += __shfl_xor_sync(0xffffffffu, rs0, 2);
        rs1 += __shfl_xor_sync(0xffffffffu, rs1, 1);
        rs1 += __shfl_xor_sync(0xffffffffu, rs1, 2);
        l0 = l0 * al0 + rs0;
        l1 = l1 * al1 + rs1;
#pragma unroll
        for (int nt = 0; nt < 8; nt++) {
            oacc[nt][0] *= al0; oacc[nt][1] *= al0;
            oacc[nt][2] *= al1; oacc[nt][3] *= al1;
        }
        __syncwarp();

#pragma unroll
        for (int ks = 0; ks < 64; ks += 8) {
            uint32_t a[4];
            a[0] = Ps[(wm + g) * AP + ks + tig];
            a[1] = Ps[(wm + g + 8) * AP + ks + tig];
            a[2] = Ps[(wm + g) * AP + ks + tig + 4];
            a[3] = Ps[(wm + g + 8) * AP + ks + tig + 4];
#pragma unroll
            for (int nt = 0; nt < 8; nt++) {
                uint32_t b0 = Vt[(nt * 8 + g) * AP + ks + tig];
                uint32_t b1 = Vt[(nt * 8 + g) * AP + ks + tig + 4];
                mma8(oacc[nt], a, b0, b1);
            }
        }
    }

    const float iv0 = 1.0f / l0, iv1 = 1.0f / l1;
#pragma unroll
    for (int nt = 0; nt < 8; nt++) {
        int col = nt * 8 + 2 * tig;
        float2 v0, v1;
        v0.x = oacc[nt][0] * iv0; v0.y = oacc[nt][1] * iv0;
        v1.x = oacc[nt][2] * iv1; v1.y = oacc[nt][3] * iv1;
        *reinterpret_cast<float2*>(O + ((size_t)bh * SEQ + rg0) * HDIM + col) = v0;
        *reinterpret_cast<float2*>(O + ((size_t)bh * SEQ + rg1) * HDIM + col) = v1;
    }
}

// ---------------- launcher ----------------
extern "C" void kernel_launch(void* const* d_in, const int* in_sizes, int n_in,
                              void* d_out, int out_size)
{
    const float* x     = (const float*)d_in[0];
    const float* qkv_w = (const float*)d_in[1];
    const float* qkv_b = (const float*)d_in[2];
    const float* out_w = (const float*)d_in[3];
    const float* out_b = (const float*)d_in[4];
    float* out = (float*)d_out;

    float *qkv, *q, *k, *v, *o;
    cudaGetSymbolAddress((void**)&qkv, g_qkv);
    cudaGetSymbolAddress((void**)&q,   g_q);
    cudaGetSymbolAddress((void**)&k,   g_k);
    cudaGetSymbolAddress((void**)&v,   g_v);
    cudaGetSymbolAddress((void**)&o,   g_o);

    cudaFuncSetAttribute(gemm_tf32_pipe<false>,
                         cudaFuncAttributeMaxDynamicSharedMemorySize, GEMM_SMEM);
    cudaFuncSetAttribute(gemm_tf32_pipe<true>,
                         cudaFuncAttributeMaxDynamicSharedMemorySize, GEMM_SMEM);
    cudaFuncSetAttribute(attn_tc_kernel,
                         cudaFuncAttributeMaxDynamicSharedMemorySize, ATTN_SMEM);

    // 1) QKV projection: [4096,1024] @ [3072,1024]^T + bias
    dim3 g1(QKVN / 128, MROWS / 128);
    gemm_tf32_pipe<false><<<g1, 256, GEMM_SMEM>>>(x, qkv_w, qkv_b, qkv,
                                                  MROWS, QKVN, DMODEL);

    // 2) RoPE + split into [B,H,S,Hd]
    int nrope = MROWS * NHEADS * (HDIM / 2);
    rope_split_kernel<<<(nrope + 255) / 256, 256>>>(qkv, q, k, v);

    // 3) causal flash attention (tf32 mma.sync)
    dim3 ga(SEQ / 128, BHT);
    attn_tc_kernel<<<ga, 256, ATTN_SMEM>>>(q, k, v, o);

    // 4) output projection with fused head-gather:
    //    [4096,1024(from g_o's B,H,S,Hd)] @ [1024,1024]^T + bias
    dim3 g2(DMODEL / 128, MROWS / 128);
    gemm_tf32_pipe<true><<<g2, 256, GEMM_SMEM>>>(o, out_w, out_b, out,
                                                 MROWS, DMODEL, DMODEL);
}

// round 11
// speedup vs baseline: 1.3616x; 1.3616x over previous
#include <cuda_runtime.h>
#include <math.h>
#include <float.h>
#include <stdint.h>

#define BATCH   2
#define SEQ     2048
#define DMODEL  1024
#define NHEADS  16
#define HDIM    64
#define MROWS   (BATCH*SEQ)     // 4096
#define QKVN    (3*DMODEL)      // 3072
#define BHT     (BATCH*NHEADS)  // 32

// ---------------- scratch (device globals; no allocations allowed) ----------
static __device__ float g_qkv[(size_t)MROWS * QKVN];
static __device__ float g_q  [(size_t)BHT * SEQ * HDIM];
static __device__ float g_k  [(size_t)BHT * SEQ * HDIM];
static __device__ float g_v  [(size_t)BHT * SEQ * HDIM];
static __device__ float g_o  [(size_t)BHT * SEQ * HDIM];

// ---------------- helpers ----------------
__device__ __forceinline__ uint32_t f2tf(float f) {
    uint32_t u;
    asm("cvt.rna.tf32.f32 %0, %1;" : "=r"(u) : "f"(f));
    return u;
}

__device__ __forceinline__ uint32_t smem_u32(const void* p) {
    uint32_t a;
    asm("{ .reg .u64 t; cvta.to.shared.u64 t, %1; cvt.u32.u64 %0, t; }" : "=r"(a) : "l"(p));
    return a;
}

__device__ __forceinline__ void cp_async16(uint32_t dst, const void* src) {
    asm volatile("cp.async.ca.shared.global [%0], [%1], 16;" :: "r"(dst), "l"(src) : "memory");
}
#define CP_COMMIT() asm volatile("cp.async.commit_group;" ::: "memory")
#define CP_WAIT(n)  asm volatile("cp.async.wait_group %0;" :: "n"(n) : "memory")

// ldmatrix x4 (b16 view of tf32 data): 4 8x8-b16 matrices -> 4 regs/lane
__device__ __forceinline__ void ldsm_x4(uint32_t* r, uint32_t addr) {
    asm volatile("ldmatrix.sync.aligned.m8n8.x4.shared.b16 {%0,%1,%2,%3}, [%4];"
        : "=r"(r[0]), "=r"(r[1]), "=r"(r[2]), "=r"(r[3]) : "r"(addr));
}

// D = A(16x8) * B(8x8) + D, tf32 in / fp32 out  (legacy tensor pipe)
__device__ __forceinline__ void mma8(float* d, const uint32_t* a, uint32_t b0, uint32_t b1) {
    asm volatile(
        "mma.sync.aligned.m16n8k8.row.col.f32.tf32.tf32.f32 "
        "{%0,%1,%2,%3}, {%4,%5,%6,%7}, {%8,%9}, {%0,%1,%2,%3};"
        : "+f"(d[0]), "+f"(d[1]), "+f"(d[2]), "+f"(d[3])
        : "r"(a[0]), "r"(a[1]), "r"(a[2]), "r"(a[3]), "r"(b0), "r"(b1));
}

// ============ TF32 mma.sync GEMM: cp.async pipeline + ldmatrix fragments ====
// C[M,N] = A[M,K] * B[N,K]^T + bias[N]. 128x128 CTA tile, k16 stages.
// 256 threads = 8 warps (2m x 4n), warp tile 64x32, 2 CTAs/SM.
// SMEM: [row][16 k-floats], 64B rows; 16B chunk c swizzled by c ^ ((row>>1)&3)
// -> every ldmatrix 8-row phase hits 8 distinct 16B bank groups.
// GATHER: A rows read from g_o's [B,H,S,Hd] layout (fused head gather);
// a 16B chunk never crosses a 64-wide head boundary.
#define STAGES  4
#define STG_B   8192                          // bytes per operand-stage
#define GEMM_SMEM (2 * STAGES * STG_B)        // 65536

template<bool GATHER>
__global__ __launch_bounds__(256, 2)
void gemm_tf32_pipe(const float* __restrict__ A, const float* __restrict__ B,
                    const float* __restrict__ bias, float* __restrict__ C,
                    int M, int N, int K)
{
    extern __shared__ float sm_f[];
    const uint32_t sbase = smem_u32(sm_f);
    const int tid  = threadIdx.x;
    const int warp = tid >> 5, lane = tid & 31;
    const int g    = lane >> 2, tig = lane & 3;
    const int wm   = (warp >> 2) * 64;
    const int wn   = (warp & 3) * 32;
    const int bm   = blockIdx.y * 128;
    const int bn   = blockIdx.x * 128;

    // producer mapping: thread -> (row = tid>>1, chunks {tid&1, (tid&1)+2})
    const int prow = tid >> 1;
    const int pc0  = tid & 1;
    const int psw  = (prow >> 1) & 3;
    const uint32_t pd0 = (uint32_t)(prow * 64 + (( pc0      ^ psw) << 4));
    const uint32_t pd1 = (uint32_t)(prow * 64 + (((pc0 + 2) ^ psw) << 4));

    // A-row source pointer (optionally head-gathered from [B,H,S,Hd])
    auto a_src = [&](int row, int kcol) -> const float* {
        if (!GATHER) {
            return A + (size_t)(bm + row) * K + kcol;
        } else {
            int m = bm + row;
            int b = m >> 11, s = m & 2047;
            int h = kcol >> 6, hd = kcol & 63;
            return A + ((((size_t)(b * NHEADS + h) << 11) + s) << 6) + hd;
        }
    };

    auto issue = [&](int ch) {
        const int st = ch & (STAGES - 1);
        const int k0 = ch << 4;
        const uint32_t ab = sbase + st * STG_B;
        const uint32_t bb = sbase + STAGES * STG_B + st * STG_B;
        cp_async16(ab + pd0, a_src(prow, k0 + pc0 * 4));
        cp_async16(ab + pd1, a_src(prow, k0 + (pc0 + 2) * 4));
        const float* brow = B + (size_t)(bn + prow) * K + k0;
        cp_async16(bb + pd0, brow + pc0 * 4);
        cp_async16(bb + pd1, brow + (pc0 + 2) * 4);
        CP_COMMIT();
    };

    // consumer: precomputed stage-relative ldmatrix byte offsets
    // A (x4): lanes 0-7 m0 rows/chunk cs, 8-15 m0+8/cs, 16-23 m0/cs+1, 24-31 m0+8/cs+1
    uint32_t offA[4][2];
#pragma unroll
    for (int mt = 0; mt < 4; mt++) {
        int rowA = wm + mt * 16 + (lane & 15);
        int sw = (rowA >> 1) & 3;
#pragma unroll
        for (int h = 0; h < 2; h++) {
            int ck = h * 2 + (lane >> 4);
            offA[mt][h] = (uint32_t)(rowA * 64 + ((ck ^ sw) << 4));
        }
    }
    // B (x4 covering two 8-wide n-tiles): lanes 0-7 n0/cs, 8-15 n0/cs+1,
    // 16-23 n0+8/cs, 24-31 n0+8/cs+1
    uint32_t offB[2][2];
#pragma unroll
    for (int pr = 0; pr < 2; pr++) {
        int rowB = wn + pr * 16 + ((lane >> 4) << 3) + (lane & 7);
        int sw = (rowB >> 1) & 3;
#pragma unroll
        for (int h = 0; h < 2; h++) {
            int ck = h * 2 + ((lane >> 3) & 1);
            offB[pr][h] = (uint32_t)(rowB * 64 + ((ck ^ sw) << 4));
        }
    }

    float acc[4][4][4];
#pragma unroll
    for (int mt = 0; mt < 4; mt++)
#pragma unroll
        for (int nt = 0; nt < 4; nt++)
#pragma unroll
            for (int j = 0; j < 4; j++) acc[mt][nt][j] = 0.f;

    const int nch = K >> 4;   // 64
    issue(0); issue(1); issue(2);

    for (int ch = 0; ch < nch; ch++) {
        CP_WAIT(2);
        __syncthreads();
        const uint32_t aS = sbase + (ch & (STAGES - 1)) * STG_B;
        const uint32_t bS = sbase + STAGES * STG_B + (ch & (STAGES - 1)) * STG_B;

#pragma unroll
        for (int h = 0; h < 2; h++) {
            uint32_t af[4][4], bf[2][4];
#pragma unroll
            for (int mt = 0; mt < 4; mt++) {
                ldsm_x4(af[mt], aS + offA[mt][h]);
#pragma unroll
                for (int j = 0; j < 4; j++) af[mt][j] = f2tf(__uint_as_float(af[mt][j]));
            }
#pragma unroll
            for (int pr = 0; pr < 2; pr++) {
                ldsm_x4(bf[pr], bS + offB[pr][h]);
#pragma unroll
                for (int j = 0; j < 4; j++) bf[pr][j] = f2tf(__uint_as_float(bf[pr][j]));
            }
#pragma unroll
            for (int pr = 0; pr < 2; pr++)
#pragma unroll
                for (int sub = 0; sub < 2; sub++) {
                    const int nt = pr * 2 + sub;
#pragma unroll
                    for (int mt = 0; mt < 4; mt++)
                        mma8(acc[mt][nt], af[mt], bf[pr][sub * 2], bf[pr][sub * 2 + 1]);
                }
        }
        if (ch + 3 < nch) issue(ch + 3);
    }

#pragma unroll
    for (int nt = 0; nt < 4; nt++) {
        int cc = bn + wn + nt * 8 + 2 * tig;
        float bv0 = bias[cc], bv1 = bias[cc + 1];
#pragma unroll
        for (int mt = 0; mt < 4; mt++) {
            int rr = bm + wm + mt * 16 + g;
            float2 v0, v1;
            v0.x = acc[mt][nt][0] + bv0; v0.y = acc[mt][nt][1] + bv1;
            v1.x = acc[mt][nt][2] + bv0; v1.y = acc[mt][nt][3] + bv1;
            *reinterpret_cast<float2*>(C + (size_t)rr * N + cc)       = v0;
            *reinterpret_cast<float2*>(C + (size_t)(rr + 8) * N + cc) = v1;
        }
    }
}

// ---------------- RoPE + split qkv[M,3*D] -> q/k/v [B,H,S,Hd] ----------------
__global__ void rope_split_kernel(const float* __restrict__ qkv,
                                  float* __restrict__ q, float* __restrict__ k,
                                  float* __restrict__ v)
{
    int idx = blockIdx.x * blockDim.x + threadIdx.x;
    if (idx >= MROWS * NHEADS * (HDIM / 2)) return;
    int j = idx & 31;
    int h = (idx >> 5) & 15;
    int m = idx >> 9;
    int b = m >> 11;
    int s = m & 2047;

    float inv_freq = 1.0f / powf(10000.0f, (float)j * (1.0f / 32.0f));
    float ang = (float)s * inv_freq;
    float sn, c;
    sincosf(ang, &sn, &c);

    size_t ib = (size_t)m * QKVN + (size_t)h * HDIM;
    size_t ob = ((size_t)(b * NHEADS + h) * SEQ + s) * HDIM;

    float q1 = qkv[ib + j],          q2 = qkv[ib + 32 + j];
    q[ob + j]      = q1 * c  - q2 * sn;
    q[ob + 32 + j] = q1 * sn + q2 * c;

    float k1 = qkv[ib + DMODEL + j], k2 = qkv[ib + DMODEL + 32 + j];
    k[ob + j]      = k1 * c  - k2 * sn;
    k[ob + 32 + j] = k1 * sn + k2 * c;

    v[ob + j]      = qkv[ib + 2 * DMODEL + j];
    v[ob + 32 + j] = qkv[ib + 2 * DMODEL + 32 + j];
}

// ============ TF32 mma.sync causal flash attention (proven, unchanged) ======
#define AP 68
#define ATTN_SMEM ((128 + 64 + 64 + 128) * AP * 4)
__global__ __launch_bounds__(256)
void attn_tc_kernel(const float* __restrict__ Q, const float* __restrict__ K,
                    const float* __restrict__ V, float* __restrict__ O)
{
    extern __shared__ uint32_t sm_u[];
    uint32_t* Qs = sm_u;
    uint32_t* Ks = Qs + 128 * AP;
    uint32_t* Vt = Ks + 64 * AP;
    uint32_t* Ps = Vt + 64 * AP;

    const int tid  = threadIdx.x;
    const int warp = tid >> 5, lane = tid & 31;
    const int g    = lane >> 2, tig = lane & 3;
    const int wm   = warp * 16;
    const int bh   = blockIdx.y;
    const int qi   = gridDim.x - 1 - blockIdx.x;
    const int q0   = qi * 128;

    const float* Qb = Q + (size_t)bh * SEQ * HDIM;
    const float* Kb = K + (size_t)bh * SEQ * HDIM;
    const float* Vb = V + (size_t)bh * SEQ * HDIM;

#pragma unroll
    for (int p = 0; p < 8; p++) {
        int idx = tid + p * 256;
        int row = idx >> 4, c4 = (idx & 15) << 2;
        float4 val = *reinterpret_cast<const float4*>(Qb + (size_t)(q0 + row) * HDIM + c4);
        uint4 u;
        u.x = f2tf(val.x); u.y = f2tf(val.y); u.z = f2tf(val.z); u.w = f2tf(val.w);
        *reinterpret_cast<uint4*>(&Qs[row * AP + c4]) = u;
    }

    float oacc[8][4];
#pragma unroll
    for (int nt = 0; nt < 8; nt++)
#pragma unroll
        for (int j = 0; j < 4; j++) oacc[nt][j] = 0.f;
    float m0 = -1e30f, m1 = -1e30f, l0 = 0.f, l1 = 0.f;

    const int vk = tid & 63;
    const int vd = (tid >> 6) << 2;
    const int rg0 = q0 + wm + g;
    const int rg1 = rg0 + 8;

    const int nkt = (q0 >> 6) + 2;
    for (int kt = 0; kt < nkt; kt++) {
        const int kg = kt << 6;
        __syncthreads();
#pragma unroll
        for (int p = 0; p < 4; p++) {
            int idx = tid + p * 256;
            int row = idx >> 4, c4 = (idx & 15) << 2;
            float4 kv = *reinterpret_cast<const float4*>(Kb + (size_t)(kg + row) * HDIM + c4);
            uint4 u;
            u.x = f2tf(kv.x); u.y = f2tf(kv.y); u.z = f2tf(kv.z); u.w = f2tf(kv.w);
            *reinterpret_cast<uint4*>(&Ks[row * AP + c4]) = u;
        }
#pragma unroll
        for (int p = 0; p < 4; p++) {
            int d4 = vd + p * 16;
            float4 vv = *reinterpret_cast<const float4*>(Vb + (size_t)(kg + vk) * HDIM + d4);
            Vt[(d4 + 0) * AP + vk] = f2tf(vv.x);
            Vt[(d4 + 1) * AP + vk] = f2tf(vv.y);
            Vt[(d4 + 2) * AP + vk] = f2tf(vv.z);
            Vt[(d4 + 3) * AP + vk] = f2tf(vv.w);
        }
        __syncthreads();

        float sacc[8][4];
#pragma unroll
        for (int nt = 0; nt < 8; nt++)
#pragma unroll
            for (int j = 0; j < 4; j++) sacc[nt][j] = 0.f;
#pragma unroll
        for (int ks = 0; ks < 64; ks += 8) {
            uint32_t a[4];
            a[0] = Qs[(wm + g) * AP + ks + tig];
            a[1] = Qs[(wm + g + 8) * AP + ks + tig];
            a[2] = Qs[(wm + g) * AP + ks + tig + 4];
            a[3] = Qs[(wm + g + 8) * AP + ks + tig + 4];
#pragma unroll
            for (int nt = 0; nt < 8; nt++) {
                uint32_t b0 = Ks[(nt * 8 + g) * AP + ks + tig];
                uint32_t b1 = Ks[(nt * 8 + g) * AP + ks + tig + 4];
                mma8(sacc[nt], a, b0, b1);
            }
        }
        const bool need_mask = (kg + 63) > rg0;
#pragma unroll
        for (int nt = 0; nt < 8; nt++) {
#pragma unroll
            for (int j = 0; j < 4; j++) sacc[nt][j] *= 0.125f;
            if (need_mask) {
                int cg = kg + nt * 8 + 2 * tig;
                if (cg     > rg0) sacc[nt][0] = -1e30f;
                if (cg + 1 > rg0) sacc[nt][1] = -1e30f;
                if (cg     > rg1) sacc[nt][2] = -1e30f;
                if (cg + 1 > rg1) sacc[nt][3] = -1e30f;
            }
        }

        float rmax0 = -1e30f, rmax1 = -1e30f;
#pragma unroll
        for (int nt = 0; nt < 8; nt++) {
            rmax0 = fmaxf(rmax0, fmaxf(sacc[nt][0], sacc[nt][1]));
            rmax1 = fmaxf(rmax1, fmaxf(sacc[nt][2], sacc[nt][3]));
        }
        rmax0 = fmaxf(rmax0, __shfl_xor_sync(0xffffffffu, rmax0, 1));
        rmax0 = fmaxf(rmax0, __shfl_xor_sync(0xffffffffu, rmax0, 2));
        rmax1 = fmaxf(rmax1, __shfl_xor_sync(0xffffffffu, rmax1, 1));
        rmax1 = fmaxf(rmax1, __shfl_xor_sync(0xffffffffu, rmax1, 2));

        float mn0 = fmaxf(m0, rmax0), mn1 = fmaxf(m1, rmax1);
        float al0 = __expf(m0 - mn0), al1 = __expf(m1 - mn1);
        m0 = mn0; m1 = mn1;

        float rs0 = 0.f, rs1 = 0.f;
#pragma unroll
        for (int nt = 0; nt < 8; nt++) {
            float p0 = __expf(sacc[nt][0] - mn0);
            float p1 = __expf(sacc[nt][1] - mn0);
            float p2 = __expf(sacc[nt][2] - mn1);
            float p3 = __expf(sacc[nt][3] - mn1);
            rs0 += p0 + p1; rs1 += p2 + p3;
            int col = nt * 8 + 2 * tig;
            uint2 u01, u23;
            u01.x = f2tf(p0); u01.y = f2tf(p1);
            u23.x = f2tf(p2); u23.y = f2tf(p3);
            *reinterpret_cast<uint2*>(&Ps[(wm + g) * AP + col])     = u01;
            *reinterpret_cast<uint2*>(&Ps[(wm + g + 8) * AP + col]) = u23;
        }
        rs0 += __shfl_xor_sync(0xffffffffu, rs0, 1);
        rs0 += __shfl_xor_sync(0xffffffffu, rs0, 2);
        rs1 += __shfl_xor_sync(0xffffffffu, rs1, 1);
        rs1 += __shfl_xor_sync(0xffffffffu, rs1, 2);
        l0 = l0 * al0 + rs0;
        l1 = l1 * al1 + rs1;
#pragma unroll
        for (int nt = 0; nt < 8; nt++) {
            oacc[nt][0] *= al0; oacc[nt][1] *= al0;
            oacc[nt][2] *= al1; oacc[nt][3] *= al1;
        }
        __syncwarp();

#pragma unroll
        for (int ks = 0; ks < 64; ks += 8) {
            uint32_t a[4];
            a[0] = Ps[(wm + g) * AP + ks + tig];
            a[1] = Ps[(wm + g + 8) * AP + ks + tig];
            a[2] = Ps[(wm + g) * AP + ks + tig + 4];
            a[3] = Ps[(wm + g + 8) * AP + ks + tig + 4];
#pragma unroll
            for (int nt = 0; nt < 8; nt++) {
                uint32_t b0 = Vt[(nt * 8 + g) * AP + ks + tig];
                uint32_t b1 = Vt[(nt * 8 + g) * AP + ks + tig + 4];
                mma8(oacc[nt], a, b0, b1);
            }
        }
    }

    const float iv0 = 1.0f / l0, iv1 = 1.0f / l1;
#pragma unroll
    for (int nt = 0; nt < 8; nt++) {
        int col = nt * 8 + 2 * tig;
        float2 v0, v1;
        v0.x = oacc[nt][0] * iv0; v0.y = oacc[nt][1] * iv0;
        v1.x = oacc[nt][2] * iv1; v1.y = oacc[nt][3] * iv1;
        *reinterpret_cast<float2*>(O + ((size_t)bh * SEQ + rg0) * HDIM + col) = v0;
        *reinterpret_cast<float2*>(O + ((size_t)bh * SEQ + rg1) * HDIM + col) = v1;
    }
}

// ---------------- launcher ----------------
extern "C" void kernel_launch(void* const* d_in, const int* in_sizes, int n_in,
                              void* d_out, int out_size)
{
    const float* x     = (const float*)d_in[0];
    const float* qkv_w = (const float*)d_in[1];
    const float* qkv_b = (const float*)d_in[2];
    const float* out_w = (const float*)d_in[3];
    const float* out_b = (const float*)d_in[4];
    float* out = (float*)d_out;

    float *qkv, *q, *k, *v, *o;
    cudaGetSymbolAddress((void**)&qkv, g_qkv);
    cudaGetSymbolAddress((void**)&q,   g_q);
    cudaGetSymbolAddress((void**)&k,   g_k);
    cudaGetSymbolAddress((void**)&v,   g_v);
    cudaGetSymbolAddress((void**)&o,   g_o);

    cudaFuncSetAttribute(gemm_tf32_pipe<false>,
                         cudaFuncAttributeMaxDynamicSharedMemorySize, GEMM_SMEM);
    cudaFuncSetAttribute(gemm_tf32_pipe<true>,
                         cudaFuncAttributeMaxDynamicSharedMemorySize, GEMM_SMEM);
    cudaFuncSetAttribute(attn_tc_kernel,
                         cudaFuncAttributeMaxDynamicSharedMemorySize, ATTN_SMEM);

    // 1) QKV projection: [4096,1024] @ [3072,1024]^T + bias
    dim3 g1(QKVN / 128, MROWS / 128);
    gemm_tf32_pipe<false><<<g1, 256, GEMM_SMEM>>>(x, qkv_w, qkv_b, qkv,
                                                  MROWS, QKVN, DMODEL);

    // 2) RoPE + split into [B,H,S,Hd]
    int nrope = MROWS * NHEADS * (HDIM / 2);
    rope_split_kernel<<<(nrope + 255) / 256, 256>>>(qkv, q, k, v);

    // 3) causal flash attention (tf32 mma.sync)
    dim3 ga(SEQ / 128, BHT);
    attn_tc_kernel<<<ga, 256, ATTN_SMEM>>>(q, k, v, o);

    // 4) output projection with fused head-gather:
    //    [4096,1024(from g_o's B,H,S,Hd)] @ [1024,1024]^T + bias
    dim3 g2(DMODEL / 128, MROWS / 128);
    gemm_tf32_pipe<true><<<g2, 256, GEMM_SMEM>>>(o, out_w, out_b, out,
                                                 MROWS, DMODEL, DMODEL);
}

// round 12
// speedup vs baseline: 1.3701x; 1.0062x over previous
#include <cuda_runtime.h>
#include <math.h>
#include <float.h>
#include <stdint.h>

#define BATCH   2
#define SEQ     2048
#define DMODEL  1024
#define NHEADS  16
#define HDIM    64
#define MROWS   (BATCH*SEQ)     // 4096
#define QKVN    (3*DMODEL)      // 3072
#define BHT     (BATCH*NHEADS)  // 32

// ---------------- scratch (device globals; no allocations allowed) ----------
static __device__ float g_qkv[(size_t)MROWS * QKVN];
static __device__ float g_q  [(size_t)BHT * SEQ * HDIM];
static __device__ float g_k  [(size_t)BHT * SEQ * HDIM];
static __device__ float g_v  [(size_t)BHT * SEQ * HDIM];
static __device__ float g_o  [(size_t)BHT * SEQ * HDIM];
static __device__ float g_xr [(size_t)MROWS * DMODEL];    // tf32-rounded x
static __device__ float g_qwr[(size_t)QKVN * DMODEL];     // tf32-rounded qkv_w
static __device__ float g_owr[(size_t)DMODEL * DMODEL];   // tf32-rounded out_w

// ---------------- helpers ----------------
__device__ __forceinline__ uint32_t f2tf(float f) {
    uint32_t u;
    asm("cvt.rna.tf32.f32 %0, %1;" : "=r"(u) : "f"(f));
    return u;
}

__device__ __forceinline__ uint32_t smem_u32(const void* p) {
    uint32_t a;
    asm("{ .reg .u64 t; cvta.to.shared.u64 t, %1; cvt.u32.u64 %0, t; }" : "=r"(a) : "l"(p));
    return a;
}

__device__ __forceinline__ void cp_async16(uint32_t dst, const void* src) {
    asm volatile("cp.async.ca.shared.global [%0], [%1], 16;" :: "r"(dst), "l"(src) : "memory");
}
#define CP_COMMIT() asm volatile("cp.async.commit_group;" ::: "memory")
#define CP_WAIT(n)  asm volatile("cp.async.wait_group %0;" :: "n"(n) : "memory")

// ldmatrix x4 (b16 view of tf32 data): 4 8x8-b16 matrices -> 4 regs/lane
__device__ __forceinline__ void ldsm_x4(uint32_t* r, uint32_t addr) {
    asm volatile("ldmatrix.sync.aligned.m8n8.x4.shared.b16 {%0,%1,%2,%3}, [%4];"
        : "=r"(r[0]), "=r"(r[1]), "=r"(r[2]), "=r"(r[3]) : "r"(addr));
}

// D = A(16x8) * B(8x8) + D, tf32 in / fp32 out  (legacy tensor pipe)
__device__ __forceinline__ void mma8(float* d, const uint32_t* a, uint32_t b0, uint32_t b1) {
    asm volatile(
        "mma.sync.aligned.m16n8k8.row.col.f32.tf32.tf32.f32 "
        "{%0,%1,%2,%3}, {%4,%5,%6,%7}, {%8,%9}, {%0,%1,%2,%3};"
        : "+f"(d[0]), "+f"(d[1]), "+f"(d[2]), "+f"(d[3])
        : "r"(a[0]), "r"(a[1]), "r"(a[2]), "r"(a[3]), "r"(b0), "r"(b1));
}

// ---------------- tf32 pre-rounding pass ----------------
__global__ void round_tf32_kernel(const float* __restrict__ in,
                                  float* __restrict__ out, int n4)
{
    int i = blockIdx.x * blockDim.x + threadIdx.x;
    if (i >= n4) return;
    float4 v = reinterpret_cast<const float4*>(in)[i];
    uint4 u;
    u.x = f2tf(v.x); u.y = f2tf(v.y); u.z = f2tf(v.z); u.w = f2tf(v.w);
    reinterpret_cast<uint4*>(out)[i] = u;
}

// ============ TF32 mma.sync GEMM: cp.async pipeline + ldmatrix fragments ====
// Inputs are PRE-ROUNDED to tf32 -> no cvt in the hot loop.
// C[M,N] = A[M,K] * B[N,K]^T + bias[N]. 128x128 CTA tile, k16 stages.
// 256 threads = 8 warps (2m x 4n), warp tile 64x32, 2 CTAs/SM.
// SMEM: [row][16 k-floats], 64B rows; 16B chunk c swizzled by c ^ ((row>>1)&3).
#define STAGES  4
#define STG_B   8192
#define GEMM_SMEM (2 * STAGES * STG_B)        // 65536

template<bool GATHER>
__global__ __launch_bounds__(256, 2)
void gemm_tf32_pipe(const float* __restrict__ A, const float* __restrict__ B,
                    const float* __restrict__ bias, float* __restrict__ C,
                    int M, int N, int K)
{
    extern __shared__ float sm_f[];
    const uint32_t sbase = smem_u32(sm_f);
    const int tid  = threadIdx.x;
    const int warp = tid >> 5, lane = tid & 31;
    const int g    = lane >> 2, tig = lane & 3;
    const int wm   = (warp >> 2) * 64;
    const int wn   = (warp & 3) * 32;
    const int bm   = blockIdx.y * 128;
    const int bn   = blockIdx.x * 128;

    const int prow = tid >> 1;
    const int pc0  = tid & 1;
    const int psw  = (prow >> 1) & 3;
    const uint32_t pd0 = (uint32_t)(prow * 64 + (( pc0      ^ psw) << 4));
    const uint32_t pd1 = (uint32_t)(prow * 64 + (((pc0 + 2) ^ psw) << 4));

    auto a_src = [&](int row, int kcol) -> const float* {
        if (!GATHER) {
            return A + (size_t)(bm + row) * K + kcol;
        } else {
            int m = bm + row;
            int b = m >> 11, s = m & 2047;
            int h = kcol >> 6, hd = kcol & 63;
            return A + ((((size_t)(b * NHEADS + h) << 11) + s) << 6) + hd;
        }
    };

    auto issue = [&](int ch) {
        const int st = ch & (STAGES - 1);
        const int k0 = ch << 4;
        const uint32_t ab = sbase + st * STG_B;
        const uint32_t bb = sbase + STAGES * STG_B + st * STG_B;
        cp_async16(ab + pd0, a_src(prow, k0 + pc0 * 4));
        cp_async16(ab + pd1, a_src(prow, k0 + (pc0 + 2) * 4));
        const float* brow = B + (size_t)(bn + prow) * K + k0;
        cp_async16(bb + pd0, brow + pc0 * 4);
        cp_async16(bb + pd1, brow + (pc0 + 2) * 4);
        CP_COMMIT();
    };

    uint32_t offA[4][2];
#pragma unroll
    for (int mt = 0; mt < 4; mt++) {
        int rowA = wm + mt * 16 + (lane & 15);
        int sw = (rowA >> 1) & 3;
#pragma unroll
        for (int h = 0; h < 2; h++) {
            int ck = h * 2 + (lane >> 4);
            offA[mt][h] = (uint32_t)(rowA * 64 + ((ck ^ sw) << 4));
        }
    }
    uint32_t offB[2][2];
#pragma unroll
    for (int pr = 0; pr < 2; pr++) {
        int rowB = wn + pr * 16 + ((lane >> 4) << 3) + (lane & 7);
        int sw = (rowB >> 1) & 3;
#pragma unroll
        for (int h = 0; h < 2; h++) {
            int ck = h * 2 + ((lane >> 3) & 1);
            offB[pr][h] = (uint32_t)(rowB * 64 + ((ck ^ sw) << 4));
        }
    }

    float acc[4][4][4];
#pragma unroll
    for (int mt = 0; mt < 4; mt++)
#pragma unroll
        for (int nt = 0; nt < 4; nt++)
#pragma unroll
            for (int j = 0; j < 4; j++) acc[mt][nt][j] = 0.f;

    const int nch = K >> 4;
    issue(0); issue(1); issue(2);

    for (int ch = 0; ch < nch; ch++) {
        CP_WAIT(2);
        __syncthreads();
        const uint32_t aS = sbase + (ch & (STAGES - 1)) * STG_B;
        const uint32_t bS = sbase + STAGES * STG_B + (ch & (STAGES - 1)) * STG_B;

#pragma unroll
        for (int h = 0; h < 2; h++) {
            uint32_t af[4][4], bf[2][4];
#pragma unroll
            for (int mt = 0; mt < 4; mt++) ldsm_x4(af[mt], aS + offA[mt][h]);
#pragma unroll
            for (int pr = 0; pr < 2; pr++) ldsm_x4(bf[pr], bS + offB[pr][h]);
#pragma unroll
            for (int pr = 0; pr < 2; pr++)
#pragma unroll
                for (int sub = 0; sub < 2; sub++) {
                    const int nt = pr * 2 + sub;
#pragma unroll
                    for (int mt = 0; mt < 4; mt++)
                        mma8(acc[mt][nt], af[mt], bf[pr][sub * 2], bf[pr][sub * 2 + 1]);
                }
        }
        if (ch + 3 < nch) issue(ch + 3);
    }

#pragma unroll
    for (int nt = 0; nt < 4; nt++) {
        int cc = bn + wn + nt * 8 + 2 * tig;
        float bv0 = bias[cc], bv1 = bias[cc + 1];
#pragma unroll
        for (int mt = 0; mt < 4; mt++) {
            int rr = bm + wm + mt * 16 + g;
            float2 v0, v1;
            v0.x = acc[mt][nt][0] + bv0; v0.y = acc[mt][nt][1] + bv1;
            v1.x = acc[mt][nt][2] + bv0; v1.y = acc[mt][nt][3] + bv1;
            *reinterpret_cast<float2*>(C + (size_t)rr * N + cc)       = v0;
            *reinterpret_cast<float2*>(C + (size_t)(rr + 8) * N + cc) = v1;
        }
    }
}

// ---------------- RoPE + split -> tf32-ROUNDED q/k/v [B,H,S,Hd] -------------
__global__ void rope_split_kernel(const float* __restrict__ qkv,
                                  float* __restrict__ q, float* __restrict__ k,
                                  float* __restrict__ v)
{
    int idx = blockIdx.x * blockDim.x + threadIdx.x;
    if (idx >= MROWS * NHEADS * (HDIM / 2)) return;
    int j = idx & 31;
    int h = (idx >> 5) & 15;
    int m = idx >> 9;
    int b = m >> 11;
    int s = m & 2047;

    float inv_freq = 1.0f / powf(10000.0f, (float)j * (1.0f / 32.0f));
    float ang = (float)s * inv_freq;
    float sn, c;
    sincosf(ang, &sn, &c);

    size_t ib = (size_t)m * QKVN + (size_t)h * HDIM;
    size_t ob = ((size_t)(b * NHEADS + h) * SEQ + s) * HDIM;

    uint32_t* qu = reinterpret_cast<uint32_t*>(q);
    uint32_t* ku = reinterpret_cast<uint32_t*>(k);
    uint32_t* vu = reinterpret_cast<uint32_t*>(v);

    float q1 = qkv[ib + j],          q2 = qkv[ib + 32 + j];
    qu[ob + j]      = f2tf(q1 * c  - q2 * sn);
    qu[ob + 32 + j] = f2tf(q1 * sn + q2 * c);

    float k1 = qkv[ib + DMODEL + j], k2 = qkv[ib + DMODEL + 32 + j];
    ku[ob + j]      = f2tf(k1 * c  - k2 * sn);
    ku[ob + 32 + j] = f2tf(k1 * sn + k2 * c);

    vu[ob + j]      = f2tf(qkv[ib + 2 * DMODEL + j]);
    vu[ob + 32 + j] = f2tf(qkv[ib + 2 * DMODEL + 32 + j]);
}

// ============ TF32 mma.sync causal flash attention, ldmatrix fragments ======
// Inputs pre-rounded tf32. BQ=128, BK=64, 8 warps, warp owns 16 q-rows.
// SMEM rows = 256B (64 floats); 16B chunk c swizzled by c ^ (row&7)
// -> each ldmatrix phase (8 rows, same chunk idx) hits 8 distinct banksets.
// Layout (bytes): Qs@0 [128], Ks@32768 [64], Vt@49152 [64][d][kcol], Ps@65536 [128]
#define ATTN_SMEM 98304
__device__ __forceinline__ uint32_t aswz(int row, int col) {  // col in floats
    return (uint32_t)(row * 256 + ((((col >> 2) ^ (row & 7))) << 4) + ((col & 3) << 2));
}

__global__ __launch_bounds__(256, 2)
void attn_tc_kernel(const float* __restrict__ Q, const float* __restrict__ K,
                    const float* __restrict__ V, float* __restrict__ O)
{
    extern __shared__ char sm_c[];
    const uint32_t sb = smem_u32(sm_c);
    const uint32_t sQ = sb, sK = sb + 32768, sV = sb + 49152, sP = sb + 65536;

    const int tid  = threadIdx.x;
    const int warp = tid >> 5, lane = tid & 31;
    const int g    = lane >> 2, tig = lane & 3;
    const int wm   = warp * 16;
    const int bh   = blockIdx.y;
    const int qi   = gridDim.x - 1 - blockIdx.x;   // heavy blocks first
    const int q0   = qi * 128;

    const float* Qb = Q + (size_t)bh * SEQ * HDIM;
    const float* Kb = K + (size_t)bh * SEQ * HDIM;
    const float* Vb = V + (size_t)bh * SEQ * HDIM;

    // load Q tile (pure copy, pre-rounded)
#pragma unroll
    for (int p = 0; p < 8; p++) {
        int idx = tid + p * 256;
        int row = idx >> 4, ck = idx & 15;
        float4 val = *reinterpret_cast<const float4*>(Qb + (size_t)(q0 + row) * HDIM + ck * 4);
        *reinterpret_cast<float4*>(sm_c + row * 256 + ((ck ^ (row & 7)) << 4)) = val;
    }

    // per-thread ldmatrix address pieces
    const int arow = wm + (lane & 15);          // A-side row (Q / P)
    const uint32_t abase = (uint32_t)(arow * 256);
    const int asw  = arow & 7;
    const int ahsel = lane >> 4;
    int brow_[4], bsw_[4];
#pragma unroll
    for (int pr = 0; pr < 4; pr++) {
        brow_[pr] = pr * 16 + ((lane >> 4) << 3) + (lane & 7);
        bsw_[pr]  = brow_[pr] & 7;
    }
    const int bhsel = (lane >> 3) & 1;

    float oacc[8][4];
#pragma unroll
    for (int nt = 0; nt < 8; nt++)
#pragma unroll
        for (int j = 0; j < 4; j++) oacc[nt][j] = 0.f;
    float m0 = -1e30f, m1 = -1e30f, l0 = 0.f, l1 = 0.f;

    const int vk = tid & 63;
    const int vd = (tid >> 6) << 2;
    const int rg0 = q0 + wm + g;
    const int rg1 = rg0 + 8;

    const int nkt = (q0 >> 6) + 2;
    for (int kt = 0; kt < nkt; kt++) {
        const int kg = kt << 6;
        __syncthreads();
        // K tile (pure copy)
#pragma unroll
        for (int p = 0; p < 4; p++) {
            int idx = tid + p * 256;
            int row = idx >> 4, ck = idx & 15;
            float4 kv = *reinterpret_cast<const float4*>(Kb + (size_t)(kg + row) * HDIM + ck * 4);
            *reinterpret_cast<float4*>(sm_c + 32768 + row * 256 + ((ck ^ (row & 7)) << 4)) = kv;
        }
        // V tile transposed to [d][kcol] (pure copy, scalar stores)
#pragma unroll
        for (int p = 0; p < 4; p++) {
            int d4 = vd + p * 16;
            float4 vv = *reinterpret_cast<const float4*>(Vb + (size_t)(kg + vk) * HDIM + d4);
            *reinterpret_cast<float*>(sm_c + 49152 + aswz(d4 + 0, vk)) = vv.x;
            *reinterpret_cast<float*>(sm_c + 49152 + aswz(d4 + 1, vk)) = vv.y;
            *reinterpret_cast<float*>(sm_c + 49152 + aswz(d4 + 2, vk)) = vv.z;
            *reinterpret_cast<float*>(sm_c + 49152 + aswz(d4 + 3, vk)) = vv.w;
        }
        __syncthreads();

        // S = Q K^T
        float sacc[8][4];
#pragma unroll
        for (int nt = 0; nt < 8; nt++)
#pragma unroll
            for (int j = 0; j < 4; j++) sacc[nt][j] = 0.f;
#pragma unroll
        for (int ks = 0; ks < 64; ks += 8) {
            uint32_t a[4];
            ldsm_x4(a, sQ + abase + ((((ks >> 2) + ahsel) ^ asw) << 4));
#pragma unroll
            for (int pr = 0; pr < 4; pr++) {
                uint32_t bf[4];
                ldsm_x4(bf, sK + (uint32_t)(brow_[pr] * 256)
                              + ((((ks >> 2) + bhsel) ^ bsw_[pr]) << 4));
                mma8(sacc[pr * 2 + 0], a, bf[0], bf[1]);
                mma8(sacc[pr * 2 + 1], a, bf[2], bf[3]);
            }
        }
        const bool need_mask = (kg + 63) > rg0;
#pragma unroll
        for (int nt = 0; nt < 8; nt++) {
#pragma unroll
            for (int j = 0; j < 4; j++) sacc[nt][j] *= 0.125f;
            if (need_mask) {
                int cg = kg + nt * 8 + 2 * tig;
                if (cg     > rg0) sacc[nt][0] = -1e30f;
                if (cg + 1 > rg0) sacc[nt][1] = -1e30f;
                if (cg     > rg1) sacc[nt][2] = -1e30f;
                if (cg + 1 > rg1) sacc[nt][3] = -1e30f;
            }
        }

        // online softmax (rows g / g+8, reduce over tig lanes)
        float rmax0 = -1e30f, rmax1 = -1e30f;
#pragma unroll
        for (int nt = 0; nt < 8; nt++) {
            rmax0 = fmaxf(rmax0, fmaxf(sacc[nt][0], sacc[nt][1]));
            rmax1 = fmaxf(rmax1, fmaxf(sacc[nt][2], sacc[nt][3]));
        }
        rmax0 = fmaxf(rmax0, __shfl_xor_sync(0xffffffffu, rmax0, 1));
        rmax0 = fmaxf(rmax0, __shfl_xor_sync(0xffffffffu, rmax0, 2));
        rmax1 = fmaxf(rmax1, __shfl_xor_sync(0xffffffffu, rmax1, 1));
        rmax1 = fmaxf(rmax1, __shfl_xor_sync(0xffffffffu, rmax1, 2));

        float mn0 = fmaxf(m0, rmax0), mn1 = fmaxf(m1, rmax1);
        float al0 = __expf(m0 - mn0), al1 = __expf(m1 - mn1);
        m0 = mn0; m1 = mn1;

        float rs0 = 0.f, rs1 = 0.f;
#pragma unroll
        for (int nt = 0; nt < 8; nt++) {
            float p0 = __expf(sacc[nt][0] - mn0);
            float p1 = __expf(sacc[nt][1] - mn0);
            float p2 = __expf(sacc[nt][2] - mn1);
            float p3 = __expf(sacc[nt][3] - mn1);
            rs0 += p0 + p1; rs1 += p2 + p3;
            int col = nt * 8 + 2 * tig;
            uint2 u01, u23;
            u01.x = f2tf(p0); u01.y = f2tf(p1);
            u23.x = f2tf(p2); u23.y = f2tf(p3);
            *reinterpret_cast<uint2*>(sm_c + 65536 + aswz(wm + g,     col)) = u01;
            *reinterpret_cast<uint2*>(sm_c + 65536 + aswz(wm + g + 8, col)) = u23;
        }
        rs0 += __shfl_xor_sync(0xffffffffu, rs0, 1);
        rs0 += __shfl_xor_sync(0xffffffffu, rs0, 2);
        rs1 += __shfl_xor_sync(0xffffffffu, rs1, 1);
        rs1 += __shfl_xor_sync(0xffffffffu, rs1, 2);
        l0 = l0 * al0 + rs0;
        l1 = l1 * al1 + rs1;
#pragma unroll
        for (int nt = 0; nt < 8; nt++) {
            oacc[nt][0] *= al0; oacc[nt][1] *= al0;
            oacc[nt][2] *= al1; oacc[nt][3] *= al1;
        }
        __syncwarp();   // Ps rows are warp-private

        // O += P V
#pragma unroll
        for (int ks = 0; ks < 64; ks += 8) {
            uint32_t a[4];
            ldsm_x4(a, sP + abase + ((((ks >> 2) + ahsel) ^ asw) << 4));
#pragma unroll
            for (int pr = 0; pr < 4; pr++) {
                uint32_t bf[4];
                ldsm_x4(bf, sV + (uint32_t)(brow_[pr] * 256)
                              + ((((ks >> 2) + bhsel) ^ bsw_[pr]) << 4));
                mma8(oacc[pr * 2 + 0], a, bf[0], bf[1]);
                mma8(oacc[pr * 2 + 1], a, bf[2], bf[3]);
            }
        }
    }

    // output: tf32-rounded (GEMM2 consumes raw bits)
    const float iv0 = 1.0f / l0, iv1 = 1.0f / l1;
    uint32_t* Ou = reinterpret_cast<uint32_t*>(O);
#pragma unroll
    for (int nt = 0; nt < 8; nt++) {
        int col = nt * 8 + 2 * tig;
        uint2 v0, v1;
        v0.x = f2tf(oacc[nt][0] * iv0); v0.y = f2tf(oacc[nt][1] * iv0);
        v1.x = f2tf(oacc[nt][2] * iv1); v1.y = f2tf(oacc[nt][3] * iv1);
        *reinterpret_cast<uint2*>(Ou + ((size_t)bh * SEQ + rg0) * HDIM + col) = v0;
        *reinterpret_cast<uint2*>(Ou + ((size_t)bh * SEQ + rg1) * HDIM + col) = v1;
    }
}

// ---------------- launcher ----------------
extern "C" void kernel_launch(void* const* d_in, const int* in_sizes, int n_in,
                              void* d_out, int out_size)
{
    const float* x     = (const float*)d_in[0];
    const float* qkv_w = (const float*)d_in[1];
    const float* qkv_b = (const float*)d_in[2];
    const float* out_w = (const float*)d_in[3];
    const float* out_b = (const float*)d_in[4];
    float* out = (float*)d_out;

    float *qkv, *q, *k, *v, *o, *xr, *qwr, *owr;
    cudaGetSymbolAddress((void**)&qkv, g_qkv);
    cudaGetSymbolAddress((void**)&q,   g_q);
    cudaGetSymbolAddress((void**)&k,   g_k);
    cudaGetSymbolAddress((void**)&v,   g_v);
    cudaGetSymbolAddress((void**)&o,   g_o);
    cudaGetSymbolAddress((void**)&xr,  g_xr);
    cudaGetSymbolAddress((void**)&qwr, g_qwr);
    cudaGetSymbolAddress((void**)&owr, g_owr);

    cudaFuncSetAttribute(gemm_tf32_pipe<false>,
                         cudaFuncAttributeMaxDynamicSharedMemorySize, GEMM_SMEM);
    cudaFuncSetAttribute(gemm_tf32_pipe<true>,
                         cudaFuncAttributeMaxDynamicSharedMemorySize, GEMM_SMEM);
    cudaFuncSetAttribute(attn_tc_kernel,
                         cudaFuncAttributeMaxDynamicSharedMemorySize, ATTN_SMEM);

    // 0) pre-round operands to tf32 (values identical to previous per-load cvt)
    round_tf32_kernel<<<(MROWS * DMODEL / 4 + 255) / 256, 256>>>(x, xr, MROWS * DMODEL / 4);
    round_tf32_kernel<<<(QKVN * DMODEL / 4 + 255) / 256, 256>>>(qkv_w, qwr, QKVN * DMODEL / 4);
    round_tf32_kernel<<<(DMODEL * DMODEL / 4 + 255) / 256, 256>>>(out_w, owr, DMODEL * DMODEL / 4);

    // 1) QKV projection
    dim3 g1(QKVN / 128, MROWS / 128);
    gemm_tf32_pipe<false><<<g1, 256, GEMM_SMEM>>>(xr, qwr, qkv_b, qkv,
                                                  MROWS, QKVN, DMODEL);

    // 2) RoPE + split (writes tf32-rounded q/k/v)
    int nrope = MROWS * NHEADS * (HDIM / 2);
    rope_split_kernel<<<(nrope + 255) / 256, 256>>>(qkv, q, k, v);

    // 3) causal flash attention (ldmatrix + mma.sync)
    dim3 ga(SEQ / 128, BHT);
    attn_tc_kernel<<<ga, 256, ATTN_SMEM>>>(q, k, v, o);

    // 4) output projection with fused head-gather
    dim3 g2(DMODEL / 128, MROWS / 128);
    gemm_tf32_pipe<true><<<g2, 256, GEMM_SMEM>>>(o, owr, out_b, out,
                                                 MROWS, DMODEL, DMODEL);
}

// round 14
// speedup vs baseline: 1.4536x; 1.0610x over previous
#include <cuda_runtime.h>
#include <math.h>
#include <float.h>
#include <stdint.h>

#define BATCH   2
#define SEQ     2048
#define DMODEL  1024
#define NHEADS  16
#define HDIM    64
#define MROWS   (BATCH*SEQ)     // 4096
#define QKVN    (3*DMODEL)      // 3072
#define BHT     (BATCH*NHEADS)  // 32

// ---------------- scratch (device globals; no allocations allowed) ----------
static __device__ float g_qkv[(size_t)MROWS * QKVN];
static __device__ float g_q  [(size_t)BHT * SEQ * HDIM];
static __device__ float g_k  [(size_t)BHT * SEQ * HDIM];
static __device__ float g_v  [(size_t)BHT * SEQ * HDIM];
static __device__ float g_o  [(size_t)BHT * SEQ * HDIM];
static __device__ float g_xr [(size_t)MROWS * DMODEL];    // tf32-rounded x
static __device__ float g_qwr[(size_t)QKVN * DMODEL];     // tf32-rounded qkv_w
static __device__ float g_owr[(size_t)DMODEL * DMODEL];   // tf32-rounded out_w

// ---------------- helpers ----------------
__device__ __forceinline__ uint32_t f2tf(float f) {
    uint32_t u;
    asm("cvt.rna.tf32.f32 %0, %1;" : "=r"(u) : "f"(f));
    return u;
}

__device__ __forceinline__ uint32_t smem_u32(const void* p) {
    uint32_t a;
    asm("{ .reg .u64 t; cvta.to.shared.u64 t, %1; cvt.u32.u64 %0, t; }" : "=r"(a) : "l"(p));
    return a;
}

__device__ __forceinline__ void cp_async16(uint32_t dst, const void* src) {
    asm volatile("cp.async.ca.shared.global [%0], [%1], 16;" :: "r"(dst), "l"(src) : "memory");
}
#define CP_COMMIT() asm volatile("cp.async.commit_group;" ::: "memory")
#define CP_WAIT(n)  asm volatile("cp.async.wait_group %0;" :: "n"(n) : "memory")

// ldmatrix x4 (b16 view of tf32 data): 4 8x8-b16 matrices -> 4 regs/lane
__device__ __forceinline__ void ldsm_x4(uint32_t* r, uint32_t addr) {
    asm volatile("ldmatrix.sync.aligned.m8n8.x4.shared.b16 {%0,%1,%2,%3}, [%4];"
        : "=r"(r[0]), "=r"(r[1]), "=r"(r[2]), "=r"(r[3]) : "r"(addr));
}

// D = A(16x8) * B(8x8) + D, tf32 in / fp32 out  (legacy tensor pipe)
__device__ __forceinline__ void mma8(float* d, const uint32_t* a, uint32_t b0, uint32_t b1) {
    asm volatile(
        "mma.sync.aligned.m16n8k8.row.col.f32.tf32.tf32.f32 "
        "{%0,%1,%2,%3}, {%4,%5,%6,%7}, {%8,%9}, {%0,%1,%2,%3};"
        : "+f"(d[0]), "+f"(d[1]), "+f"(d[2]), "+f"(d[3])
        : "r"(a[0]), "r"(a[1]), "r"(a[2]), "r"(a[3]), "r"(b0), "r"(b1));
}

// ---------------- tf32 pre-rounding pass ----------------
__global__ void round_tf32_kernel(const float* __restrict__ in,
                                  float* __restrict__ out, int n4)
{
    int i = blockIdx.x * blockDim.x + threadIdx.x;
    if (i >= n4) return;
    float4 v = reinterpret_cast<const float4*>(in)[i];
    uint4 u;
    u.x = f2tf(v.x); u.y = f2tf(v.y); u.z = f2tf(v.z); u.w = f2tf(v.w);
    reinterpret_cast<uint4*>(out)[i] = u;
}

// ============ TF32 mma.sync GEMM: cp.async pipeline + ldmatrix fragments ====
// Inputs PRE-ROUNDED to tf32. C[M,N] = A[M,K] * B[N,K]^T + bias[N].
// CTA tile 128(M) x 256(N), k16 stages, 256 threads = 8 warps (2m x 4n),
// warp tile 64x64 -> 8 LDSM per 32 MMAs (0.25/MMA, crossbar below tensor floor).
// SMEM: [row][16 k-floats], 64B rows; 16B chunk c swizzled by c ^ ((row>>1)&3).
// A side (tile, producer, fragments) is IDENTICAL to the proven R12 code.
#define STAGES   4
#define A_STG_B  8192            // 128 rows * 64B
#define B_STG_B  16384           // 256 rows * 64B
#define GEMM_SMEM (STAGES * (A_STG_B + B_STG_B))   // 98304

template<bool GATHER>
__global__ __launch_bounds__(256)
void gemm_tf32_pipe(const float* __restrict__ A, const float* __restrict__ B,
                    const float* __restrict__ bias, float* __restrict__ C,
                    int M, int N, int K)
{
    extern __shared__ float sm_f[];
    const uint32_t sbase = smem_u32(sm_f);
    const int tid  = threadIdx.x;
    const int warp = tid >> 5, lane = tid & 31;
    const int g    = lane >> 2, tig = lane & 3;
    const int wm   = (warp >> 2) * 64;     // 2 m-warps (as R12)
    const int wn   = (warp & 3) * 64;      // 4 n-warps, 64-wide each
    const int bm   = blockIdx.y * 128;
    const int bn   = blockIdx.x * 256;

    // producer mapping (R12 exact for A): row = tid>>1, chunks {tid&1, (tid&1)+2}
    const int prow = tid >> 1;             // 0..127
    const int pc0  = tid & 1;
    const int psw  = (prow >> 1) & 3;      // note: ((prow+128)>>1)&3 == psw
    const uint32_t pd0 = (uint32_t)(prow * 64 + (( pc0      ^ psw) << 4));
    const uint32_t pd1 = (uint32_t)(prow * 64 + (((pc0 + 2) ^ psw) << 4));

    auto a_src = [&](int row, int kcol) -> const float* {
        if (!GATHER) {
            return A + (size_t)(bm + row) * K + kcol;
        } else {
            int m = bm + row;
            int b = m >> 11, s = m & 2047;
            int h = kcol >> 6, hd = kcol & 63;
            return A + ((((size_t)(b * NHEADS + h) << 11) + s) << 6) + hd;
        }
    };

    auto issue = [&](int ch) {
        const int st = ch & (STAGES - 1);
        const int k0 = ch << 4;
        const uint32_t ab = sbase + st * A_STG_B;
        const uint32_t bb = sbase + STAGES * A_STG_B + st * B_STG_B;
        // A tile: 128 rows (R12 exact)
        cp_async16(ab + pd0, a_src(prow, k0 + pc0 * 4));
        cp_async16(ab + pd1, a_src(prow, k0 + (pc0 + 2) * 4));
        // B tile: 256 rows -> rows prow and prow+128 (same swizzle: +128 keeps (row>>1)&3)
        const float* br0 = B + (size_t)(bn + prow) * K + k0;
        const float* br1 = B + (size_t)(bn + prow + 128) * K + k0;
        cp_async16(bb + pd0, br0 + pc0 * 4);
        cp_async16(bb + pd1, br0 + (pc0 + 2) * 4);
        cp_async16(bb + 128 * 64 + pd0, br1 + pc0 * 4);
        cp_async16(bb + 128 * 64 + pd1, br1 + (pc0 + 2) * 4);
        CP_COMMIT();
    };

    // consumer ldmatrix offsets (A: R12 exact; B: same formula, pr extended to 4)
    uint32_t offA[4][2];
#pragma unroll
    for (int mt = 0; mt < 4; mt++) {
        int rowA = wm + mt * 16 + (lane & 15);
        int sw = (rowA >> 1) & 3;
#pragma unroll
        for (int h = 0; h < 2; h++) {
            int ck = h * 2 + (lane >> 4);
            offA[mt][h] = (uint32_t)(rowA * 64 + ((ck ^ sw) << 4));
        }
    }
    uint32_t offB[4][2];
#pragma unroll
    for (int pr = 0; pr < 4; pr++) {
        int rowB = wn + pr * 16 + ((lane >> 4) << 3) + (lane & 7);
        int sw = (rowB >> 1) & 3;
#pragma unroll
        for (int h = 0; h < 2; h++) {
            int ck = h * 2 + ((lane >> 3) & 1);
            offB[pr][h] = (uint32_t)(rowB * 64 + ((ck ^ sw) << 4));
        }
    }

    float acc[4][8][4];
#pragma unroll
    for (int mt = 0; mt < 4; mt++)
#pragma unroll
        for (int nt = 0; nt < 8; nt++)
#pragma unroll
            for (int j = 0; j < 4; j++) acc[mt][nt][j] = 0.f;

    const int nch = K >> 4;
    issue(0); issue(1); issue(2);

    for (int ch = 0; ch < nch; ch++) {
        CP_WAIT(2);
        __syncthreads();
        const uint32_t aS = sbase + (ch & (STAGES - 1)) * A_STG_B;
        const uint32_t bS = sbase + STAGES * A_STG_B + (ch & (STAGES - 1)) * B_STG_B;

#pragma unroll
        for (int h = 0; h < 2; h++) {
            uint32_t af[4][4], bf[4][4];
#pragma unroll
            for (int mt = 0; mt < 4; mt++) ldsm_x4(af[mt], aS + offA[mt][h]);
#pragma unroll
            for (int pr = 0; pr < 4; pr++) ldsm_x4(bf[pr], bS + offB[pr][h]);
#pragma unroll
            for (int pr = 0; pr < 4; pr++)
#pragma unroll
                for (int sub = 0; sub < 2; sub++) {
                    const int nt = pr * 2 + sub;
#pragma unroll
                    for (int mt = 0; mt < 4; mt++)
                        mma8(acc[mt][nt], af[mt], bf[pr][sub * 2], bf[pr][sub * 2 + 1]);
                }
        }
        if (ch + 3 < nch) issue(ch + 3);
    }

#pragma unroll
    for (int nt = 0; nt < 8; nt++) {
        int cc = bn + wn + nt * 8 + 2 * tig;
        float bv0 = bias[cc], bv1 = bias[cc + 1];
#pragma unroll
        for (int mt = 0; mt < 4; mt++) {
            int rr = bm + wm + mt * 16 + g;
            float2 v0, v1;
            v0.x = acc[mt][nt][0] + bv0; v0.y = acc[mt][nt][1] + bv1;
            v1.x = acc[mt][nt][2] + bv0; v1.y = acc[mt][nt][3] + bv1;
            *reinterpret_cast<float2*>(C + (size_t)rr * N + cc)       = v0;
            *reinterpret_cast<float2*>(C + (size_t)(rr + 8) * N + cc) = v1;
        }
    }
}

// ---------------- RoPE + split -> tf32-ROUNDED q/k/v [B,H,S,Hd] -------------
__global__ void rope_split_kernel(const float* __restrict__ qkv,
                                  float* __restrict__ q, float* __restrict__ k,
                                  float* __restrict__ v)
{
    int idx = blockIdx.x * blockDim.x + threadIdx.x;
    if (idx >= MROWS * NHEADS * (HDIM / 2)) return;
    int j = idx & 31;
    int h = (idx >> 5) & 15;
    int m = idx >> 9;
    int b = m >> 11;
    int s = m & 2047;

    float inv_freq = 1.0f / powf(10000.0f, (float)j * (1.0f / 32.0f));
    float ang = (float)s * inv_freq;
    float sn, c;
    sincosf(ang, &sn, &c);

    size_t ib = (size_t)m * QKVN + (size_t)h * HDIM;
    size_t ob = ((size_t)(b * NHEADS + h) * SEQ + s) * HDIM;

    uint32_t* qu = reinterpret_cast<uint32_t*>(q);
    uint32_t* ku = reinterpret_cast<uint32_t*>(k);
    uint32_t* vu = reinterpret_cast<uint32_t*>(v);

    float q1 = qkv[ib + j],          q2 = qkv[ib + 32 + j];
    qu[ob + j]      = f2tf(q1 * c  - q2 * sn);
    qu[ob + 32 + j] = f2tf(q1 * sn + q2 * c);

    float k1 = qkv[ib + DMODEL + j], k2 = qkv[ib + DMODEL + 32 + j];
    ku[ob + j]      = f2tf(k1 * c  - k2 * sn);
    ku[ob + 32 + j] = f2tf(k1 * sn + k2 * c);

    vu[ob + j]      = f2tf(qkv[ib + 2 * DMODEL + j]);
    vu[ob + 32 + j] = f2tf(qkv[ib + 2 * DMODEL + 32 + j]);
}

// ============ TF32 mma.sync causal flash attention (R12 verbatim) ===========
// Inputs pre-rounded tf32. BQ=128, BK=64, 8 warps, warp owns 16 q-rows.
// SMEM rows = 256B (64 floats); 16B chunk c swizzled by c ^ (row&7).
// Layout (bytes): Qs@0 [128], Ks@32768 [64], Vt@49152 [64][d][kcol], Ps@65536 [128]
#define ATTN_SMEM 98304
__device__ __forceinline__ uint32_t aswz(int row, int col) {  // col in floats
    return (uint32_t)(row * 256 + ((((col >> 2) ^ (row & 7))) << 4) + ((col & 3) << 2));
}

__global__ __launch_bounds__(256, 2)
void attn_tc_kernel(const float* __restrict__ Q, const float* __restrict__ K,
                    const float* __restrict__ V, float* __restrict__ O)
{
    extern __shared__ char sm_c[];
    const uint32_t sb = smem_u32(sm_c);
    const uint32_t sQ = sb, sK = sb + 32768, sV = sb + 49152, sP = sb + 65536;

    const int tid  = threadIdx.x;
    const int warp = tid >> 5, lane = tid & 31;
    const int g    = lane >> 2, tig = lane & 3;
    const int wm   = warp * 16;
    const int bh   = blockIdx.y;
    const int qi   = gridDim.x - 1 - blockIdx.x;   // heavy blocks first
    const int q0   = qi * 128;

    const float* Qb = Q + (size_t)bh * SEQ * HDIM;
    const float* Kb = K + (size_t)bh * SEQ * HDIM;
    const float* Vb = V + (size_t)bh * SEQ * HDIM;

    // load Q tile (pure copy, pre-rounded)
#pragma unroll
    for (int p = 0; p < 8; p++) {
        int idx = tid + p * 256;
        int row = idx >> 4, ck = idx & 15;
        float4 val = *reinterpret_cast<const float4*>(Qb + (size_t)(q0 + row) * HDIM + ck * 4);
        *reinterpret_cast<float4*>(sm_c + row * 256 + ((ck ^ (row & 7)) << 4)) = val;
    }

    // per-thread ldmatrix address pieces
    const int arow = wm + (lane & 15);          // A-side row (Q / P)
    const uint32_t abase = (uint32_t)(arow * 256);
    const int asw  = arow & 7;
    const int ahsel = lane >> 4;
    int brow_[4], bsw_[4];
#pragma unroll
    for (int pr = 0; pr < 4; pr++) {
        brow_[pr] = pr * 16 + ((lane >> 4) << 3) + (lane & 7);
        bsw_[pr]  = brow_[pr] & 7;
    }
    const int bhsel = (lane >> 3) & 1;

    float oacc[8][4];
#pragma unroll
    for (int nt = 0; nt < 8; nt++)
#pragma unroll
        for (int j = 0; j < 4; j++) oacc[nt][j] = 0.f;
    float m0 = -1e30f, m1 = -1e30f, l0 = 0.f, l1 = 0.f;

    const int vk = tid & 63;
    const int vd = (tid >> 6) << 2;
    const int rg0 = q0 + wm + g;
    const int rg1 = rg0 + 8;

    const int nkt = (q0 >> 6) + 2;
    for (int kt = 0; kt < nkt; kt++) {
        const int kg = kt << 6;
        __syncthreads();
        // K tile (pure copy)
#pragma unroll
        for (int p = 0; p < 4; p++) {
            int idx = tid + p * 256;
            int row = idx >> 4, ck = idx & 15;
            float4 kv = *reinterpret_cast<const float4*>(Kb + (size_t)(kg + row) * HDIM + ck * 4);
            *reinterpret_cast<float4*>(sm_c + 32768 + row * 256 + ((ck ^ (row & 7)) << 4)) = kv;
        }
        // V tile transposed to [d][kcol]
#pragma unroll
        for (int p = 0; p < 4; p++) {
            int d4 = vd + p * 16;
            float4 vv = *reinterpret_cast<const float4*>(Vb + (size_t)(kg + vk) * HDIM + d4);
            *reinterpret_cast<float*>(sm_c + 49152 + aswz(d4 + 0, vk)) = vv.x;
            *reinterpret_cast<float*>(sm_c + 49152 + aswz(d4 + 1, vk)) = vv.y;
            *reinterpret_cast<float*>(sm_c + 49152 + aswz(d4 + 2, vk)) = vv.z;
            *reinterpret_cast<float*>(sm_c + 49152 + aswz(d4 + 3, vk)) = vv.w;
        }
        __syncthreads();

        // S = Q K^T
        float sacc[8][4];
#pragma unroll
        for (int nt = 0; nt < 8; nt++)
#pragma unroll
            for (int j = 0; j < 4; j++) sacc[nt][j] = 0.f;
#pragma unroll
        for (int ks = 0; ks < 64; ks += 8) {
            uint32_t a[4];
            ldsm_x4(a, sQ + abase + ((((ks >> 2) + ahsel) ^ asw) << 4));
#pragma unroll
            for (int pr = 0; pr < 4; pr++) {
                uint32_t bf[4];
                ldsm_x4(bf, sK + (uint32_t)(brow_[pr] * 256)
                              + ((((ks >> 2) + bhsel) ^ bsw_[pr]) << 4));
                mma8(sacc[pr * 2 + 0], a, bf[0], bf[1]);
                mma8(sacc[pr * 2 + 1], a, bf[2], bf[3]);
            }
        }
        const bool need_mask = (kg + 63) > rg0;
#pragma unroll
        for (int nt = 0; nt < 8; nt++) {
#pragma unroll
            for (int j = 0; j < 4; j++) sacc[nt][j] *= 0.125f;
            if (need_mask) {
                int cg = kg + nt * 8 + 2 * tig;
                if (cg     > rg0) sacc[nt][0] = -1e30f;
                if (cg + 1 > rg0) sacc[nt][1] = -1e30f;
                if (cg     > rg1) sacc[nt][2] = -1e30f;
                if (cg + 1 > rg1) sacc[nt][3] = -1e30f;
            }
        }

        // online softmax (rows g / g+8, reduce over tig lanes)
        float rmax0 = -1e30f, rmax1 = -1e30f;
#pragma unroll
        for (int nt = 0; nt < 8; nt++) {
            rmax0 = fmaxf(rmax0, fmaxf(sacc[nt][0], sacc[nt][1]));
            rmax1 = fmaxf(rmax1, fmaxf(sacc[nt][2], sacc[nt][3]));
        }
        rmax0 = fmaxf(rmax0, __shfl_xor_sync(0xffffffffu, rmax0, 1));
        rmax0 = fmaxf(rmax0, __shfl_xor_sync(0xffffffffu, rmax0, 2));
        rmax1 = fmaxf(rmax1, __shfl_xor_sync(0xffffffffu, rmax1, 1));
        rmax1 = fmaxf(rmax1, __shfl_xor_sync(0xffffffffu, rmax1, 2));

        float mn0 = fmaxf(m0, rmax0), mn1 = fmaxf(m1, rmax1);
        float al0 = __expf(m0 - mn0), al1 = __expf(m1 - mn1);
        m0 = mn0; m1 = mn1;

        float rs0 = 0.f, rs1 = 0.f;
#pragma unroll
        for (int nt = 0; nt < 8; nt++) {
            float p0 = __expf(sacc[nt][0] - mn0);
            float p1 = __expf(sacc[nt][1] - mn0);
            float p2 = __expf(sacc[nt][2] - mn1);
            float p3 = __expf(sacc[nt][3] - mn1);
            rs0 += p0 + p1; rs1 += p2 + p3;
            int col = nt * 8 + 2 * tig;
            uint2 u01, u23;
            u01.x = f2tf(p0); u01.y = f2tf(p1);
            u23.x = f2tf(p2); u23.y = f2tf(p3);
            *reinterpret_cast<uint2*>(sm_c + 65536 + aswz(wm + g,     col)) = u01;
            *reinterpret_cast<uint2*>(sm_c + 65536 + aswz(wm + g + 8, col)) = u23;
        }
        rs0 += __shfl_xor_sync(0xffffffffu, rs0, 1);
        rs0 += __shfl_xor_sync(0xffffffffu, rs0, 2);
        rs1 += __shfl_xor_sync(0xffffffffu, rs1, 1);
        rs1 += __shfl_xor_sync(0xffffffffu, rs1, 2);
        l0 = l0 * al0 + rs0;
        l1 = l1 * al1 + rs1;
#pragma unroll
        for (int nt = 0; nt < 8; nt++) {
            oacc[nt][0] *= al0; oacc[nt][1] *= al0;
            oacc[nt][2] *= al1; oacc[nt][3] *= al1;
        }
        __syncwarp();   // Ps rows are warp-private

        // O += P V
#pragma unroll
        for (int ks = 0; ks < 64; ks += 8) {
            uint32_t a[4];
            ldsm_x4(a, sP + abase + ((((ks >> 2) + ahsel) ^ asw) << 4));
#pragma unroll
            for (int pr = 0; pr < 4; pr++) {
                uint32_t bf[4];
                ldsm_x4(bf, sV + (uint32_t)(brow_[pr] * 256)
                              + ((((ks >> 2) + bhsel) ^ bsw_[pr]) << 4));
                mma8(oacc[pr * 2 + 0], a, bf[0], bf[1]);
                mma8(oacc[pr * 2 + 1], a, bf[2], bf[3]);
            }
        }
    }

    // output: tf32-rounded (GEMM2 consumes raw bits)
    const float iv0 = 1.0f / l0, iv1 = 1.0f / l1;
    uint32_t* Ou = reinterpret_cast<uint32_t*>(O);
#pragma unroll
    for (int nt = 0; nt < 8; nt++) {
        int col = nt * 8 + 2 * tig;
        uint2 v0, v1;
        v0.x = f2tf(oacc[nt][0] * iv0); v0.y = f2tf(oacc[nt][1] * iv0);
        v1.x = f2tf(oacc[nt][2] * iv1); v1.y = f2tf(oacc[nt][3] * iv1);
        *reinterpret_cast<uint2*>(Ou + ((size_t)bh * SEQ + rg0) * HDIM + col) = v0;
        *reinterpret_cast<uint2*>(Ou + ((size_t)bh * SEQ + rg1) * HDIM + col) = v1;
    }
}

// ---------------- launcher ----------------
extern "C" void kernel_launch(void* const* d_in, const int* in_sizes, int n_in,
                              void* d_out, int out_size)
{
    const float* x     = (const float*)d_in[0];
    const float* qkv_w = (const float*)d_in[1];
    const float* qkv_b = (const float*)d_in[2];
    const float* out_w = (const float*)d_in[3];
    const float* out_b = (const float*)d_in[4];
    float* out = (float*)d_out;

    float *qkv, *q, *k, *v, *o, *xr, *qwr, *owr;
    cudaGetSymbolAddress((void**)&qkv, g_qkv);
    cudaGetSymbolAddress((void**)&q,   g_q);
    cudaGetSymbolAddress((void**)&k,   g_k);
    cudaGetSymbolAddress((void**)&v,   g_v);
    cudaGetSymbolAddress((void**)&o,   g_o);
    cudaGetSymbolAddress((void**)&xr,  g_xr);
    cudaGetSymbolAddress((void**)&qwr, g_qwr);
    cudaGetSymbolAddress((void**)&owr, g_owr);

    cudaFuncSetAttribute(gemm_tf32_pipe<false>,
                         cudaFuncAttributeMaxDynamicSharedMemorySize, GEMM_SMEM);
    cudaFuncSetAttribute(gemm_tf32_pipe<true>,
                         cudaFuncAttributeMaxDynamicSharedMemorySize, GEMM_SMEM);
    cudaFuncSetAttribute(attn_tc_kernel,
                         cudaFuncAttributeMaxDynamicSharedMemorySize, ATTN_SMEM);

    // 0) pre-round operands to tf32
    round_tf32_kernel<<<(MROWS * DMODEL / 4 + 255) / 256, 256>>>(x, xr, MROWS * DMODEL / 4);
    round_tf32_kernel<<<(QKVN * DMODEL / 4 + 255) / 256, 256>>>(qkv_w, qwr, QKVN * DMODEL / 4);
    round_tf32_kernel<<<(DMODEL * DMODEL / 4 + 255) / 256, 256>>>(out_w, owr, DMODEL * DMODEL / 4);

    // 1) QKV projection: CTA tile 128x256
    dim3 g1(QKVN / 256, MROWS / 128);
    gemm_tf32_pipe<false><<<g1, 256, GEMM_SMEM>>>(xr, qwr, qkv_b, qkv,
                                                  MROWS, QKVN, DMODEL);

    // 2) RoPE + split (writes tf32-rounded q/k/v)
    int nrope = MROWS * NHEADS * (HDIM / 2);
    rope_split_kernel<<<(nrope + 255) / 256, 256>>>(qkv, q, k, v);

    // 3) causal flash attention (R12 verbatim)
    dim3 ga(SEQ / 128, BHT);
    attn_tc_kernel<<<ga, 256, ATTN_SMEM>>>(q, k, v, o);

    // 4) output projection with fused head-gather: CTA tile 128x256
    dim3 g2(DMODEL / 256, MROWS / 128);
    gemm_tf32_pipe<true><<<g2, 256, GEMM_SMEM>>>(o, owr, out_b, out,
                                                 MROWS, DMODEL, DMODEL);
}

// round 15
// speedup vs baseline: 1.4999x; 1.0319x over previous
#include <cuda_runtime.h>
#include <math.h>
#include <float.h>
#include <stdint.h>

#define BATCH   2
#define SEQ     2048
#define DMODEL  1024
#define NHEADS  16
#define HDIM    64
#define MROWS   (BATCH*SEQ)     // 4096
#define QKVN    (3*DMODEL)      // 3072
#define BHT     (BATCH*NHEADS)  // 32

// ---------------- scratch (device globals; no allocations allowed) ----------
static __device__ float g_qkv[(size_t)MROWS * QKVN];
static __device__ float g_q  [(size_t)BHT * SEQ * HDIM];
static __device__ float g_k  [(size_t)BHT * SEQ * HDIM];
static __device__ float g_v  [(size_t)BHT * SEQ * HDIM];
static __device__ float g_o  [(size_t)BHT * SEQ * HDIM];
static __device__ float g_xr [(size_t)MROWS * DMODEL];    // tf32-rounded x
static __device__ float g_qwr[(size_t)QKVN * DMODEL];     // tf32-rounded qkv_w
static __device__ float g_owr[(size_t)DMODEL * DMODEL];   // tf32-rounded out_w

// ---------------- helpers ----------------
__device__ __forceinline__ uint32_t f2tf(float f) {
    uint32_t u;
    asm("cvt.rna.tf32.f32 %0, %1;" : "=r"(u) : "f"(f));
    return u;
}

__device__ __forceinline__ uint32_t smem_u32(const void* p) {
    uint32_t a;
    asm("{ .reg .u64 t; cvta.to.shared.u64 t, %1; cvt.u32.u64 %0, t; }" : "=r"(a) : "l"(p));
    return a;
}

__device__ __forceinline__ void cp_async16(uint32_t dst, const void* src) {
    asm volatile("cp.async.ca.shared.global [%0], [%1], 16;" :: "r"(dst), "l"(src) : "memory");
}
#define CP_COMMIT() asm volatile("cp.async.commit_group;" ::: "memory")
#define CP_WAIT(n)  asm volatile("cp.async.wait_group %0;" :: "n"(n) : "memory")

// ldmatrix x4 (b16 view of tf32 data): 4 8x8-b16 matrices -> 4 regs/lane
__device__ __forceinline__ void ldsm_x4(uint32_t* r, uint32_t addr) {
    asm volatile("ldmatrix.sync.aligned.m8n8.x4.shared.b16 {%0,%1,%2,%3}, [%4];"
        : "=r"(r[0]), "=r"(r[1]), "=r"(r[2]), "=r"(r[3]) : "r"(addr));
}

// D = A(16x8) * B(8x8) + D, tf32 in / fp32 out  (legacy tensor pipe)
__device__ __forceinline__ void mma8(float* d, const uint32_t* a, uint32_t b0, uint32_t b1) {
    asm volatile(
        "mma.sync.aligned.m16n8k8.row.col.f32.tf32.tf32.f32 "
        "{%0,%1,%2,%3}, {%4,%5,%6,%7}, {%8,%9}, {%0,%1,%2,%3};"
        : "+f"(d[0]), "+f"(d[1]), "+f"(d[2]), "+f"(d[3])
        : "r"(a[0]), "r"(a[1]), "r"(a[2]), "r"(a[3]), "r"(b0), "r"(b1));
}

// ---------------- tf32 pre-rounding pass ----------------
__global__ void round_tf32_kernel(const float* __restrict__ in,
                                  float* __restrict__ out, int n4)
{
    int i = blockIdx.x * blockDim.x + threadIdx.x;
    if (i >= n4) return;
    float4 v = reinterpret_cast<const float4*>(in)[i];
    uint4 u;
    u.x = f2tf(v.x); u.y = f2tf(v.y); u.z = f2tf(v.z); u.w = f2tf(v.w);
    reinterpret_cast<uint4*>(out)[i] = u;
}

// ============ TF32 mma.sync GEMM (R14 verbatim — proven) ====================
// CTA tile 128(M) x 256(N), k16 stages, 256 threads = 8 warps (2m x 4n),
// warp tile 64x64. SMEM: 64B rows; chunk c swizzled by c ^ ((row>>1)&3).
#define STAGES   4
#define A_STG_B  8192            // 128 rows * 64B
#define B_STG_B  16384           // 256 rows * 64B
#define GEMM_SMEM (STAGES * (A_STG_B + B_STG_B))   // 98304

template<bool GATHER>
__global__ __launch_bounds__(256)
void gemm_tf32_pipe(const float* __restrict__ A, const float* __restrict__ B,
                    const float* __restrict__ bias, float* __restrict__ C,
                    int M, int N, int K)
{
    extern __shared__ float sm_f[];
    const uint32_t sbase = smem_u32(sm_f);
    const int tid  = threadIdx.x;
    const int warp = tid >> 5, lane = tid & 31;
    const int g    = lane >> 2, tig = lane & 3;
    const int wm   = (warp >> 2) * 64;
    const int wn   = (warp & 3) * 64;
    const int bm   = blockIdx.y * 128;
    const int bn   = blockIdx.x * 256;

    const int prow = tid >> 1;
    const int pc0  = tid & 1;
    const int psw  = (prow >> 1) & 3;
    const uint32_t pd0 = (uint32_t)(prow * 64 + (( pc0      ^ psw) << 4));
    const uint32_t pd1 = (uint32_t)(prow * 64 + (((pc0 + 2) ^ psw) << 4));

    auto a_src = [&](int row, int kcol) -> const float* {
        if (!GATHER) {
            return A + (size_t)(bm + row) * K + kcol;
        } else {
            int m = bm + row;
            int b = m >> 11, s = m & 2047;
            int h = kcol >> 6, hd = kcol & 63;
            return A + ((((size_t)(b * NHEADS + h) << 11) + s) << 6) + hd;
        }
    };

    auto issue = [&](int ch) {
        const int st = ch & (STAGES - 1);
        const int k0 = ch << 4;
        const uint32_t ab = sbase + st * A_STG_B;
        const uint32_t bb = sbase + STAGES * A_STG_B + st * B_STG_B;
        cp_async16(ab + pd0, a_src(prow, k0 + pc0 * 4));
        cp_async16(ab + pd1, a_src(prow, k0 + (pc0 + 2) * 4));
        const float* br0 = B + (size_t)(bn + prow) * K + k0;
        const float* br1 = B + (size_t)(bn + prow + 128) * K + k0;
        cp_async16(bb + pd0, br0 + pc0 * 4);
        cp_async16(bb + pd1, br0 + (pc0 + 2) * 4);
        cp_async16(bb + 128 * 64 + pd0, br1 + pc0 * 4);
        cp_async16(bb + 128 * 64 + pd1, br1 + (pc0 + 2) * 4);
        CP_COMMIT();
    };

    uint32_t offA[4][2];
#pragma unroll
    for (int mt = 0; mt < 4; mt++) {
        int rowA = wm + mt * 16 + (lane & 15);
        int sw = (rowA >> 1) & 3;
#pragma unroll
        for (int h = 0; h < 2; h++) {
            int ck = h * 2 + (lane >> 4);
            offA[mt][h] = (uint32_t)(rowA * 64 + ((ck ^ sw) << 4));
        }
    }
    uint32_t offB[4][2];
#pragma unroll
    for (int pr = 0; pr < 4; pr++) {
        int rowB = wn + pr * 16 + ((lane >> 4) << 3) + (lane & 7);
        int sw = (rowB >> 1) & 3;
#pragma unroll
        for (int h = 0; h < 2; h++) {
            int ck = h * 2 + ((lane >> 3) & 1);
            offB[pr][h] = (uint32_t)(rowB * 64 + ((ck ^ sw) << 4));
        }
    }

    float acc[4][8][4];
#pragma unroll
    for (int mt = 0; mt < 4; mt++)
#pragma unroll
        for (int nt = 0; nt < 8; nt++)
#pragma unroll
            for (int j = 0; j < 4; j++) acc[mt][nt][j] = 0.f;

    const int nch = K >> 4;
    issue(0); issue(1); issue(2);

    for (int ch = 0; ch < nch; ch++) {
        CP_WAIT(2);
        __syncthreads();
        const uint32_t aS = sbase + (ch & (STAGES - 1)) * A_STG_B;
        const uint32_t bS = sbase + STAGES * A_STG_B + (ch & (STAGES - 1)) * B_STG_B;

#pragma unroll
        for (int h = 0; h < 2; h++) {
            uint32_t af[4][4], bf[4][4];
#pragma unroll
            for (int mt = 0; mt < 4; mt++) ldsm_x4(af[mt], aS + offA[mt][h]);
#pragma unroll
            for (int pr = 0; pr < 4; pr++) ldsm_x4(bf[pr], bS + offB[pr][h]);
#pragma unroll
            for (int pr = 0; pr < 4; pr++)
#pragma unroll
                for (int sub = 0; sub < 2; sub++) {
                    const int nt = pr * 2 + sub;
#pragma unroll
                    for (int mt = 0; mt < 4; mt++)
                        mma8(acc[mt][nt], af[mt], bf[pr][sub * 2], bf[pr][sub * 2 + 1]);
                }
        }
        if (ch + 3 < nch) issue(ch + 3);
    }

#pragma unroll
    for (int nt = 0; nt < 8; nt++) {
        int cc = bn + wn + nt * 8 + 2 * tig;
        float bv0 = bias[cc], bv1 = bias[cc + 1];
#pragma unroll
        for (int mt = 0; mt < 4; mt++) {
            int rr = bm + wm + mt * 16 + g;
            float2 v0, v1;
            v0.x = acc[mt][nt][0] + bv0; v0.y = acc[mt][nt][1] + bv1;
            v1.x = acc[mt][nt][2] + bv0; v1.y = acc[mt][nt][3] + bv1;
            *reinterpret_cast<float2*>(C + (size_t)rr * N + cc)       = v0;
            *reinterpret_cast<float2*>(C + (size_t)(rr + 8) * N + cc) = v1;
        }
    }
}

// ---------------- RoPE + split -> tf32-ROUNDED q/k/v [B,H,S,Hd] -------------
__global__ void rope_split_kernel(const float* __restrict__ qkv,
                                  float* __restrict__ q, float* __restrict__ k,
                                  float* __restrict__ v)
{
    int idx = blockIdx.x * blockDim.x + threadIdx.x;
    if (idx >= MROWS * NHEADS * (HDIM / 2)) return;
    int j = idx & 31;
    int h = (idx >> 5) & 15;
    int m = idx >> 9;
    int b = m >> 11;
    int s = m & 2047;

    float inv_freq = 1.0f / powf(10000.0f, (float)j * (1.0f / 32.0f));
    float ang = (float)s * inv_freq;
    float sn, c;
    sincosf(ang, &sn, &c);

    size_t ib = (size_t)m * QKVN + (size_t)h * HDIM;
    size_t ob = ((size_t)(b * NHEADS + h) * SEQ + s) * HDIM;

    uint32_t* qu = reinterpret_cast<uint32_t*>(q);
    uint32_t* ku = reinterpret_cast<uint32_t*>(k);
    uint32_t* vu = reinterpret_cast<uint32_t*>(v);

    float q1 = qkv[ib + j],          q2 = qkv[ib + 32 + j];
    qu[ob + j]      = f2tf(q1 * c  - q2 * sn);
    qu[ob + 32 + j] = f2tf(q1 * sn + q2 * c);

    float k1 = qkv[ib + DMODEL + j], k2 = qkv[ib + DMODEL + 32 + j];
    ku[ob + j]      = f2tf(k1 * c  - k2 * sn);
    ku[ob + 32 + j] = f2tf(k1 * sn + k2 * c);

    vu[ob + j]      = f2tf(qkv[ib + 2 * DMODEL + j]);
    vu[ob + 32 + j] = f2tf(qkv[ib + 2 * DMODEL + 32 + j]);
}

// ============ TF32 mma.sync causal flash attention, 4 fat warps =============
// Inputs pre-rounded tf32. BQ=128, BK=64, 128 threads = 4 warps.
// Warp owns 32 q-rows (mt in {0,1}) -> each K/V fragment reused for 2 m-tiles;
// LDSM count per CTA-iter drops 640 -> 384. 2 CTAs/SM keeps 8 warps resident.
// SMEM rows = 256B; 16B chunk c swizzled by c ^ (row&7).
// Layout (bytes): Qs@0 [128], Ks@32768 [64], Vt@49152 [64][d][kcol], Ps@65536 [128]
#define ATTN_SMEM 98304
__device__ __forceinline__ uint32_t aswz(int row, int col) {  // col in floats
    return (uint32_t)(row * 256 + ((((col >> 2) ^ (row & 7))) << 4) + ((col & 3) << 2));
}

__global__ __launch_bounds__(128, 2)
void attn_tc_kernel(const float* __restrict__ Q, const float* __restrict__ K,
                    const float* __restrict__ V, float* __restrict__ O)
{
    extern __shared__ char sm_c[];
    const uint32_t sb = smem_u32(sm_c);
    const uint32_t sQ = sb, sK = sb + 32768, sV = sb + 49152, sP = sb + 65536;

    const int tid  = threadIdx.x;
    const int warp = tid >> 5, lane = tid & 31;
    const int g    = lane >> 2, tig = lane & 3;
    const int wm   = warp * 32;                    // 4 warps x 32 q-rows
    const int bh   = blockIdx.y;
    const int qi   = gridDim.x - 1 - blockIdx.x;   // heavy blocks first
    const int q0   = qi * 128;

    const float* Qb = Q + (size_t)bh * SEQ * HDIM;
    const float* Kb = K + (size_t)bh * SEQ * HDIM;
    const float* Vb = V + (size_t)bh * SEQ * HDIM;

    // load Q tile (pure copy, pre-rounded): 128 rows x 16 chunks
#pragma unroll
    for (int p = 0; p < 16; p++) {
        int idx = tid + p * 128;
        int row = idx >> 4, ck = idx & 15;
        float4 val = *reinterpret_cast<const float4*>(Qb + (size_t)(q0 + row) * HDIM + ck * 4);
        *reinterpret_cast<float4*>(sm_c + row * 256 + ((ck ^ (row & 7)) << 4)) = val;
    }

    // A-side (Q/P) fragment address pieces, per m16 tile
    uint32_t abase[2]; int asw[2];
#pragma unroll
    for (int mt = 0; mt < 2; mt++) {
        int rowA = wm + mt * 16 + (lane & 15);
        abase[mt] = (uint32_t)(rowA * 256);
        asw[mt]   = rowA & 7;
    }
    const int ahsel = lane >> 4;
    // B-side (K/V) fragment rows: warp-independent (shared work)
    int brow_[4], bsw_[4];
#pragma unroll
    for (int pr = 0; pr < 4; pr++) {
        brow_[pr] = pr * 16 + ((lane >> 4) << 3) + (lane & 7);
        bsw_[pr]  = brow_[pr] & 7;
    }
    const int bhsel = (lane >> 3) & 1;

    float oacc[2][8][4];
#pragma unroll
    for (int mt = 0; mt < 2; mt++)
#pragma unroll
        for (int nt = 0; nt < 8; nt++)
#pragma unroll
            for (int j = 0; j < 4; j++) oacc[mt][nt][j] = 0.f;
    float mi[2][2], li[2][2];
#pragma unroll
    for (int mt = 0; mt < 2; mt++) {
        mi[mt][0] = mi[mt][1] = -1e30f;
        li[mt][0] = li[mt][1] = 0.f;
    }

    const int vk = tid & 63;            // kcol owned for V transpose
    const int vd = (tid >> 6) << 2;     // {0,4}
    int rg[2][2];
#pragma unroll
    for (int mt = 0; mt < 2; mt++) {
        rg[mt][0] = q0 + wm + mt * 16 + g;
        rg[mt][1] = rg[mt][0] + 8;
    }

    const int nkt = (q0 >> 6) + 2;
    for (int kt = 0; kt < nkt; kt++) {
        const int kg = kt << 6;
        __syncthreads();
        // K tile (pure copy): 64 rows x 16 chunks
#pragma unroll
        for (int p = 0; p < 8; p++) {
            int idx = tid + p * 128;
            int row = idx >> 4, ck = idx & 15;
            float4 kv = *reinterpret_cast<const float4*>(Kb + (size_t)(kg + row) * HDIM + ck * 4);
            *reinterpret_cast<float4*>(sm_c + 32768 + row * 256 + ((ck ^ (row & 7)) << 4)) = kv;
        }
        // V tile transposed to [d][kcol]
#pragma unroll
        for (int p = 0; p < 8; p++) {
            int d4 = vd + p * 8;
            float4 vv = *reinterpret_cast<const float4*>(Vb + (size_t)(kg + vk) * HDIM + d4);
            *reinterpret_cast<float*>(sm_c + 49152 + aswz(d4 + 0, vk)) = vv.x;
            *reinterpret_cast<float*>(sm_c + 49152 + aswz(d4 + 1, vk)) = vv.y;
            *reinterpret_cast<float*>(sm_c + 49152 + aswz(d4 + 2, vk)) = vv.z;
            *reinterpret_cast<float*>(sm_c + 49152 + aswz(d4 + 3, vk)) = vv.w;
        }
        __syncthreads();

        // S = Q K^T  (one K fragment set feeds both m-tiles)
        float sacc[2][8][4];
#pragma unroll
        for (int mt = 0; mt < 2; mt++)
#pragma unroll
            for (int nt = 0; nt < 8; nt++)
#pragma unroll
                for (int j = 0; j < 4; j++) sacc[mt][nt][j] = 0.f;
#pragma unroll
        for (int ks = 0; ks < 64; ks += 8) {
            uint32_t a[2][4];
#pragma unroll
            for (int mt = 0; mt < 2; mt++)
                ldsm_x4(a[mt], sQ + abase[mt] + ((((ks >> 2) + ahsel) ^ asw[mt]) << 4));
#pragma unroll
            for (int pr = 0; pr < 4; pr++) {
                uint32_t bf[4];
                ldsm_x4(bf, sK + (uint32_t)(brow_[pr] * 256)
                              + ((((ks >> 2) + bhsel) ^ bsw_[pr]) << 4));
#pragma unroll
                for (int mt = 0; mt < 2; mt++) {
                    mma8(sacc[mt][pr * 2 + 0], a[mt], bf[0], bf[1]);
                    mma8(sacc[mt][pr * 2 + 1], a[mt], bf[2], bf[3]);
                }
            }
        }
        // scale + causal mask (per m16-tile trigger, mirrors R14 exactly)
#pragma unroll
        for (int mt = 0; mt < 2; mt++) {
            const bool need_mask = (kg + 63) > (q0 + wm + mt * 16 + 0);
#pragma unroll
            for (int nt = 0; nt < 8; nt++) {
#pragma unroll
                for (int j = 0; j < 4; j++) sacc[mt][nt][j] *= 0.125f;
                if (need_mask) {
                    int cg = kg + nt * 8 + 2 * tig;
                    if (cg     > rg[mt][0]) sacc[mt][nt][0] = -1e30f;
                    if (cg + 1 > rg[mt][0]) sacc[mt][nt][1] = -1e30f;
                    if (cg     > rg[mt][1]) sacc[mt][nt][2] = -1e30f;
                    if (cg + 1 > rg[mt][1]) sacc[mt][nt][3] = -1e30f;
                }
            }
        }

        // online softmax per m16 tile (rows g / g+8; reduce over tig lanes)
#pragma unroll
        for (int mt = 0; mt < 2; mt++) {
            float rmax0 = -1e30f, rmax1 = -1e30f;
#pragma unroll
            for (int nt = 0; nt < 8; nt++) {
                rmax0 = fmaxf(rmax0, fmaxf(sacc[mt][nt][0], sacc[mt][nt][1]));
                rmax1 = fmaxf(rmax1, fmaxf(sacc[mt][nt][2], sacc[mt][nt][3]));
            }
            rmax0 = fmaxf(rmax0, __shfl_xor_sync(0xffffffffu, rmax0, 1));
            rmax0 = fmaxf(rmax0, __shfl_xor_sync(0xffffffffu, rmax0, 2));
            rmax1 = fmaxf(rmax1, __shfl_xor_sync(0xffffffffu, rmax1, 1));
            rmax1 = fmaxf(rmax1, __shfl_xor_sync(0xffffffffu, rmax1, 2));

            float mn0 = fmaxf(mi[mt][0], rmax0), mn1 = fmaxf(mi[mt][1], rmax1);
            float al0 = __expf(mi[mt][0] - mn0), al1 = __expf(mi[mt][1] - mn1);
            mi[mt][0] = mn0; mi[mt][1] = mn1;

            float rs0 = 0.f, rs1 = 0.f;
#pragma unroll
            for (int nt = 0; nt < 8; nt++) {
                float p0 = __expf(sacc[mt][nt][0] - mn0);
                float p1 = __expf(sacc[mt][nt][1] - mn0);
                float p2 = __expf(sacc[mt][nt][2] - mn1);
                float p3 = __expf(sacc[mt][nt][3] - mn1);
                rs0 += p0 + p1; rs1 += p2 + p3;
                int col = nt * 8 + 2 * tig;
                uint2 u01, u23;
                u01.x = f2tf(p0); u01.y = f2tf(p1);
                u23.x = f2tf(p2); u23.y = f2tf(p3);
                *reinterpret_cast<uint2*>(sm_c + 65536 + aswz(wm + mt * 16 + g,     col)) = u01;
                *reinterpret_cast<uint2*>(sm_c + 65536 + aswz(wm + mt * 16 + g + 8, col)) = u23;
            }
            rs0 += __shfl_xor_sync(0xffffffffu, rs0, 1);
            rs0 += __shfl_xor_sync(0xffffffffu, rs0, 2);
            rs1 += __shfl_xor_sync(0xffffffffu, rs1, 1);
            rs1 += __shfl_xor_sync(0xffffffffu, rs1, 2);
            li[mt][0] = li[mt][0] * al0 + rs0;
            li[mt][1] = li[mt][1] * al1 + rs1;
#pragma unroll
            for (int nt = 0; nt < 8; nt++) {
                oacc[mt][nt][0] *= al0; oacc[mt][nt][1] *= al0;
                oacc[mt][nt][2] *= al1; oacc[mt][nt][3] *= al1;
            }
        }
        __syncwarp();   // Ps rows are warp-private

        // O += P V  (one V fragment set feeds both m-tiles)
#pragma unroll
        for (int ks = 0; ks < 64; ks += 8) {
            uint32_t a[2][4];
#pragma unroll
            for (int mt = 0; mt < 2; mt++)
                ldsm_x4(a[mt], sP + abase[mt] + ((((ks >> 2) + ahsel) ^ asw[mt]) << 4));
#pragma unroll
            for (int pr = 0; pr < 4; pr++) {
                uint32_t bf[4];
                ldsm_x4(bf, sV + (uint32_t)(brow_[pr] * 256)
                              + ((((ks >> 2) + bhsel) ^ bsw_[pr]) << 4));
#pragma unroll
                for (int mt = 0; mt < 2; mt++) {
                    mma8(oacc[mt][pr * 2 + 0], a[mt], bf[0], bf[1]);
                    mma8(oacc[mt][pr * 2 + 1], a[mt], bf[2], bf[3]);
                }
            }
        }
    }

    // output: tf32-rounded (GEMM2 consumes raw bits)
    uint32_t* Ou = reinterpret_cast<uint32_t*>(O);
#pragma unroll
    for (int mt = 0; mt < 2; mt++) {
        const float iv0 = 1.0f / li[mt][0], iv1 = 1.0f / li[mt][1];
#pragma unroll
        for (int nt = 0; nt < 8; nt++) {
            int col = nt * 8 + 2 * tig;
            uint2 v0, v1;
            v0.x = f2tf(oacc[mt][nt][0] * iv0); v0.y = f2tf(oacc[mt][nt][1] * iv0);
            v1.x = f2tf(oacc[mt][nt][2] * iv1); v1.y = f2tf(oacc[mt][nt][3] * iv1);
            *reinterpret_cast<uint2*>(Ou + ((size_t)bh * SEQ + rg[mt][0]) * HDIM + col) = v0;
            *reinterpret_cast<uint2*>(Ou + ((size_t)bh * SEQ + rg[mt][1]) * HDIM + col) = v1;
        }
    }
}

// ---------------- launcher ----------------
extern "C" void kernel_launch(void* const* d_in, const int* in_sizes, int n_in,
                              void* d_out, int out_size)
{
    const float* x     = (const float*)d_in[0];
    const float* qkv_w = (const float*)d_in[1];
    const float* qkv_b = (const float*)d_in[2];
    const float* out_w = (const float*)d_in[3];
    const float* out_b = (const float*)d_in[4];
    float* out = (float*)d_out;

    float *qkv, *q, *k, *v, *o, *xr, *qwr, *owr;
    cudaGetSymbolAddress((void**)&qkv, g_qkv);
    cudaGetSymbolAddress((void**)&q,   g_q);
    cudaGetSymbolAddress((void**)&k,   g_k);
    cudaGetSymbolAddress((void**)&v,   g_v);
    cudaGetSymbolAddress((void**)&o,   g_o);
    cudaGetSymbolAddress((void**)&xr,  g_xr);
    cudaGetSymbolAddress((void**)&qwr, g_qwr);
    cudaGetSymbolAddress((void**)&owr, g_owr);

    cudaFuncSetAttribute(gemm_tf32_pipe<false>,
                         cudaFuncAttributeMaxDynamicSharedMemorySize, GEMM_SMEM);
    cudaFuncSetAttribute(gemm_tf32_pipe<true>,
                         cudaFuncAttributeMaxDynamicSharedMemorySize, GEMM_SMEM);
    cudaFuncSetAttribute(attn_tc_kernel,
                         cudaFuncAttributeMaxDynamicSharedMemorySize, ATTN_SMEM);

    // 0) pre-round operands to tf32
    round_tf32_kernel<<<(MROWS * DMODEL / 4 + 255) / 256, 256>>>(x, xr, MROWS * DMODEL / 4);
    round_tf32_kernel<<<(QKVN * DMODEL / 4 + 255) / 256, 256>>>(qkv_w, qwr, QKVN * DMODEL / 4);
    round_tf32_kernel<<<(DMODEL * DMODEL / 4 + 255) / 256, 256>>>(out_w, owr, DMODEL * DMODEL / 4);

    // 1) QKV projection: CTA tile 128x256
    dim3 g1(QKVN / 256, MROWS / 128);
    gemm_tf32_pipe<false><<<g1, 256, GEMM_SMEM>>>(xr, qwr, qkv_b, qkv,
                                                  MROWS, QKVN, DMODEL);

    // 2) RoPE + split (writes tf32-rounded q/k/v)
    int nrope = MROWS * NHEADS * (HDIM / 2);
    rope_split_kernel<<<(nrope + 255) / 256, 256>>>(qkv, q, k, v);

    // 3) causal flash attention (4 fat warps, 128 threads, 2 CTAs/SM)
    dim3 ga(SEQ / 128, BHT);
    attn_tc_kernel<<<ga, 128, ATTN_SMEM>>>(q, k, v, o);

    // 4) output projection with fused head-gather: CTA tile 128x256
    dim3 g2(DMODEL / 256, MROWS / 128);
    gemm_tf32_pipe<true><<<g2, 256, GEMM_SMEM>>>(o, owr, out_b, out,
                                                 MROWS, DMODEL, DMODEL);
}

// round 16
// speedup vs baseline: 2.1955x; 1.4637x over previous
#include <cuda_runtime.h>
#include <cuda_fp16.h>
#include <math.h>
#include <float.h>
#include <stdint.h>

#define BATCH   2
#define SEQ     2048
#define DMODEL  1024
#define NHEADS  16
#define HDIM    64
#define MROWS   (BATCH*SEQ)     // 4096
#define QKVN    (3*DMODEL)      // 3072
#define BHT     (BATCH*NHEADS)  // 32

// ---------------- scratch (device globals; no allocations allowed) ----------
static __device__ float  g_qkv[(size_t)MROWS * QKVN];            // fp32 GEMM1 out
static __device__ __half g_q  [(size_t)BHT * SEQ * HDIM];
static __device__ __half g_k  [(size_t)BHT * SEQ * HDIM];
static __device__ __half g_v  [(size_t)BHT * SEQ * HDIM];
static __device__ __half g_o  [(size_t)BHT * SEQ * HDIM];
static __device__ __half g_xh [(size_t)MROWS * DMODEL];          // fp16 x
static __device__ __half g_qwh[(size_t)QKVN * DMODEL];           // fp16 qkv_w
static __device__ __half g_owh[(size_t)DMODEL * DMODEL];         // fp16 out_w

// ---------------- helpers ----------------
__device__ __forceinline__ uint32_t smem_u32(const void* p) {
    uint32_t a;
    asm("{ .reg .u64 t; cvta.to.shared.u64 t, %1; cvt.u32.u64 %0, t; }" : "=r"(a) : "l"(p));
    return a;
}

__device__ __forceinline__ void cp_async16(uint32_t dst, const void* src) {
    asm volatile("cp.async.ca.shared.global [%0], [%1], 16;" :: "r"(dst), "l"(src) : "memory");
}
#define CP_COMMIT() asm volatile("cp.async.commit_group;" ::: "memory")
#define CP_WAIT(n)  asm volatile("cp.async.wait_group %0;" :: "n"(n) : "memory")

// ldmatrix x4: 4 8x8-b16 matrices -> 4 regs/lane (native fp16 use)
__device__ __forceinline__ void ldsm_x4(uint32_t* r, uint32_t addr) {
    asm volatile("ldmatrix.sync.aligned.m8n8.x4.shared.b16 {%0,%1,%2,%3}, [%4];"
        : "=r"(r[0]), "=r"(r[1]), "=r"(r[2]), "=r"(r[3]) : "r"(addr));
}

// D = A(16x8) * B(8x8)^T + D over k16, fp16 in / fp32 accumulate
__device__ __forceinline__ void mma16(float* d, const uint32_t* a, uint32_t b0, uint32_t b1) {
    asm volatile(
        "mma.sync.aligned.m16n8k16.row.col.f32.f16.f16.f32 "
        "{%0,%1,%2,%3}, {%4,%5,%6,%7}, {%8,%9}, {%0,%1,%2,%3};"
        : "+f"(d[0]), "+f"(d[1]), "+f"(d[2]), "+f"(d[3])
        : "r"(a[0]), "r"(a[1]), "r"(a[2]), "r"(a[3]), "r"(b0), "r"(b1));
}

// ---------------- fp16 pre-conversion pass ----------------
__global__ void round_fp16_kernel(const float* __restrict__ in,
                                  __half* __restrict__ out, int n4)
{
    int i = blockIdx.x * blockDim.x + threadIdx.x;
    if (i >= n4) return;
    float4 v = reinterpret_cast<const float4*>(in)[i];
    __half2 h0 = __floats2half2_rn(v.x, v.y);
    __half2 h1 = __floats2half2_rn(v.z, v.w);
    uint2 u;
    u.x = *reinterpret_cast<uint32_t*>(&h0);
    u.y = *reinterpret_cast<uint32_t*>(&h1);
    reinterpret_cast<uint2*>(out)[i] = u;
}

// ============ FP16 mma.sync GEMM: cp.async pipeline + ldmatrix ==============
// C[M,N] = A[M,K] * B[N,K]^T + bias[N], A/B fp16, C fp32.
// CTA tile 128(M) x 256(N), k32 chunks, 256 threads = 8 warps (2m x 4n),
// warp tile 64x64. SMEM rows = 32 fp16 (64B, 4 chunks); chunk c ^ ((row>>1)&3).
// Address formulas identical to the proven tf32 kernel (same byte geometry).
#define STAGES   4
#define A_STG_B  8192            // 128 rows * 64B
#define B_STG_B  16384           // 256 rows * 64B
#define GEMM_SMEM (STAGES * (A_STG_B + B_STG_B))   // 98304

template<bool GATHER>
__global__ __launch_bounds__(256)
void gemm_fp16_pipe(const __half* __restrict__ A, const __half* __restrict__ B,
                    const float* __restrict__ bias, float* __restrict__ C,
                    int M, int N, int K)
{
    extern __shared__ float sm_f[];
    const uint32_t sbase = smem_u32(sm_f);
    const int tid  = threadIdx.x;
    const int warp = tid >> 5, lane = tid & 31;
    const int g    = lane >> 2, tig = lane & 3;
    const int wm   = (warp >> 2) * 64;
    const int wn   = (warp & 3) * 64;
    const int bm   = blockIdx.y * 128;
    const int bn   = blockIdx.x * 256;

    const int prow = tid >> 1;
    const int pc0  = tid & 1;
    const int psw  = (prow >> 1) & 3;
    const uint32_t pd0 = (uint32_t)(prow * 64 + (( pc0      ^ psw) << 4));
    const uint32_t pd1 = (uint32_t)(prow * 64 + (((pc0 + 2) ^ psw) << 4));

    // A-row source (optionally head-gathered from [B,H,S,Hd]); kcol in fp16 elems
    auto a_src = [&](int row, int kcol) -> const __half* {
        if (!GATHER) {
            return A + (size_t)(bm + row) * K + kcol;
        } else {
            int m = bm + row;
            int b = m >> 11, s = m & 2047;
            int h = kcol >> 6, hd = kcol & 63;
            return A + ((((size_t)(b * NHEADS + h) << 11) + s) << 6) + hd;
        }
    };

    auto issue = [&](int ch) {
        const int st = ch & (STAGES - 1);
        const int k0 = ch << 5;                    // k32 fp16 per chunk
        const uint32_t ab = sbase + st * A_STG_B;
        const uint32_t bb = sbase + STAGES * A_STG_B + st * B_STG_B;
        cp_async16(ab + pd0, a_src(prow, k0 + pc0 * 8));
        cp_async16(ab + pd1, a_src(prow, k0 + (pc0 + 2) * 8));
        const __half* br0 = B + (size_t)(bn + prow) * K + k0;
        const __half* br1 = B + (size_t)(bn + prow + 128) * K + k0;
        cp_async16(bb + pd0, br0 + pc0 * 8);
        cp_async16(bb + pd1, br0 + (pc0 + 2) * 8);
        cp_async16(bb + 128 * 64 + pd0, br1 + pc0 * 8);
        cp_async16(bb + 128 * 64 + pd1, br1 + (pc0 + 2) * 8);
        CP_COMMIT();
    };

    // ldmatrix offsets (identical byte formulas to proven tf32 version)
    uint32_t offA[4][2];
#pragma unroll
    for (int mt = 0; mt < 4; mt++) {
        int rowA = wm + mt * 16 + (lane & 15);
        int sw = (rowA >> 1) & 3;
#pragma unroll
        for (int h = 0; h < 2; h++) {
            int ck = h * 2 + (lane >> 4);
            offA[mt][h] = (uint32_t)(rowA * 64 + ((ck ^ sw) << 4));
        }
    }
    uint32_t offB[4][2];
#pragma unroll
    for (int pr = 0; pr < 4; pr++) {
        int rowB = wn + pr * 16 + ((lane >> 4) << 3) + (lane & 7);
        int sw = (rowB >> 1) & 3;
#pragma unroll
        for (int h = 0; h < 2; h++) {
            int ck = h * 2 + ((lane >> 3) & 1);
            offB[pr][h] = (uint32_t)(rowB * 64 + ((ck ^ sw) << 4));
        }
    }

    float acc[4][8][4];
#pragma unroll
    for (int mt = 0; mt < 4; mt++)
#pragma unroll
        for (int nt = 0; nt < 8; nt++)
#pragma unroll
            for (int j = 0; j < 4; j++) acc[mt][nt][j] = 0.f;

    const int nch = K >> 5;                        // 32 chunks
    issue(0); issue(1); issue(2);

    for (int ch = 0; ch < nch; ch++) {
        CP_WAIT(2);
        __syncthreads();
        const uint32_t aS = sbase + (ch & (STAGES - 1)) * A_STG_B;
        const uint32_t bS = sbase + STAGES * A_STG_B + (ch & (STAGES - 1)) * B_STG_B;

#pragma unroll
        for (int h = 0; h < 2; h++) {              // two k16 blocks per chunk
            uint32_t af[4][4], bf[4][4];
#pragma unroll
            for (int mt = 0; mt < 4; mt++) ldsm_x4(af[mt], aS + offA[mt][h]);
#pragma unroll
            for (int pr = 0; pr < 4; pr++) ldsm_x4(bf[pr], bS + offB[pr][h]);
#pragma unroll
            for (int pr = 0; pr < 4; pr++)
#pragma unroll
                for (int sub = 0; sub < 2; sub++) {
                    const int nt = pr * 2 + sub;
#pragma unroll
                    for (int mt = 0; mt < 4; mt++)
                        mma16(acc[mt][nt], af[mt], bf[pr][sub * 2], bf[pr][sub * 2 + 1]);
                }
        }
        if (ch + 3 < nch) issue(ch + 3);
    }

#pragma unroll
    for (int nt = 0; nt < 8; nt++) {
        int cc = bn + wn + nt * 8 + 2 * tig;
        float bv0 = bias[cc], bv1 = bias[cc + 1];
#pragma unroll
        for (int mt = 0; mt < 4; mt++) {
            int rr = bm + wm + mt * 16 + g;
            float2 v0, v1;
            v0.x = acc[mt][nt][0] + bv0; v0.y = acc[mt][nt][1] + bv1;
            v1.x = acc[mt][nt][2] + bv0; v1.y = acc[mt][nt][3] + bv1;
            *reinterpret_cast<float2*>(C + (size_t)rr * N + cc)       = v0;
            *reinterpret_cast<float2*>(C + (size_t)(rr + 8) * N + cc) = v1;
        }
    }
}

// ---------------- RoPE + split -> fp16 q/k/v [B,H,S,Hd] ---------------------
__global__ void rope_split_kernel(const float* __restrict__ qkv,
                                  __half* __restrict__ q, __half* __restrict__ k,
                                  __half* __restrict__ v)
{
    int idx = blockIdx.x * blockDim.x + threadIdx.x;
    if (idx >= MROWS * NHEADS * (HDIM / 2)) return;
    int j = idx & 31;
    int h = (idx >> 5) & 15;
    int m = idx >> 9;
    int b = m >> 11;
    int s = m & 2047;

    float inv_freq = 1.0f / powf(10000.0f, (float)j * (1.0f / 32.0f));
    float ang = (float)s * inv_freq;
    float sn, c;
    sincosf(ang, &sn, &c);

    size_t ib = (size_t)m * QKVN + (size_t)h * HDIM;
    size_t ob = ((size_t)(b * NHEADS + h) * SEQ + s) * HDIM;

    float q1 = qkv[ib + j],          q2 = qkv[ib + 32 + j];
    q[ob + j]      = __float2half_rn(q1 * c  - q2 * sn);
    q[ob + 32 + j] = __float2half_rn(q1 * sn + q2 * c);

    float k1 = qkv[ib + DMODEL + j], k2 = qkv[ib + DMODEL + 32 + j];
    k[ob + j]      = __float2half_rn(k1 * c  - k2 * sn);
    k[ob + 32 + j] = __float2half_rn(k1 * sn + k2 * c);

    v[ob + j]      = __float2half_rn(qkv[ib + 2 * DMODEL + j]);
    v[ob + 32 + j] = __float2half_rn(qkv[ib + 2 * DMODEL + 32 + j]);
}

// ============ FP16 mma.sync causal flash attention, 4 fat warps =============
// BQ=128, BK=64, 128 threads = 4 warps, warp owns 32 q-rows (R15 structure).
// SMEM rows = 64 fp16 (128B, 8 chunks); chunk c ^ (row&7) (proven pattern).
// Layout (bytes): Qs@0 [128 rows,16K], Ks@16384 [64,8K],
//                 Vt@24576 [64 d rows][64 kcol] 8K, Ps@32768 [128,16K]
#define ATTN_SMEM 49152
__device__ __forceinline__ uint32_t aswz16(int row, int col) {  // col in fp16
    return (uint32_t)(row * 128 + ((((col >> 3) ^ (row & 7))) << 4) + ((col & 7) << 1));
}

__global__ __launch_bounds__(128, 2)
void attn_tc_kernel(const __half* __restrict__ Q, const __half* __restrict__ K,
                    const __half* __restrict__ V, __half* __restrict__ O)
{
    extern __shared__ char sm_c[];
    const uint32_t sb = smem_u32(sm_c);
    const uint32_t sQ = sb, sK = sb + 16384, sV = sb + 24576, sP = sb + 32768;

    const int tid  = threadIdx.x;
    const int warp = tid >> 5, lane = tid & 31;
    const int g    = lane >> 2, tig = lane & 3;
    const int wm   = warp * 32;
    const int bh   = blockIdx.y;
    const int qi   = gridDim.x - 1 - blockIdx.x;   // heavy blocks first
    const int q0   = qi * 128;

    const __half* Qb = Q + (size_t)bh * SEQ * HDIM;
    const __half* Kb = K + (size_t)bh * SEQ * HDIM;
    const __half* Vb = V + (size_t)bh * SEQ * HDIM;

    // load Q tile: 128 rows x 8 chunks (16B each)
#pragma unroll
    for (int p = 0; p < 8; p++) {
        int idx = tid + p * 128;
        int row = idx >> 3, ck = idx & 7;
        uint4 val = *reinterpret_cast<const uint4*>(Qb + (size_t)(q0 + row) * HDIM + ck * 8);
        *reinterpret_cast<uint4*>(sm_c + row * 128 + ((ck ^ (row & 7)) << 4)) = val;
    }

    // A-side (Q/P) fragment pieces per m16 tile
    uint32_t abase[2]; int asw[2];
#pragma unroll
    for (int mt = 0; mt < 2; mt++) {
        int rowA = wm + mt * 16 + (lane & 15);
        abase[mt] = (uint32_t)(rowA * 128);
        asw[mt]   = rowA & 7;
    }
    const int ahsel = lane >> 4;
    int brow_[4], bsw_[4];
#pragma unroll
    for (int pr = 0; pr < 4; pr++) {
        brow_[pr] = pr * 16 + ((lane >> 4) << 3) + (lane & 7);
        bsw_[pr]  = brow_[pr] & 7;
    }
    const int bhsel = (lane >> 3) & 1;

    float oacc[2][8][4];
#pragma unroll
    for (int mt = 0; mt < 2; mt++)
#pragma unroll
        for (int nt = 0; nt < 8; nt++)
#pragma unroll
            for (int j = 0; j < 4; j++) oacc[mt][nt][j] = 0.f;
    float mi[2][2], li[2][2];
#pragma unroll
    for (int mt = 0; mt < 2; mt++) {
        mi[mt][0] = mi[mt][1] = -1e30f;
        li[mt][0] = li[mt][1] = 0.f;
    }

    const int vk = tid & 63;
    const int vd = (tid >> 6) << 2;     // {0,4}
    int rg[2][2];
#pragma unroll
    for (int mt = 0; mt < 2; mt++) {
        rg[mt][0] = q0 + wm + mt * 16 + g;
        rg[mt][1] = rg[mt][0] + 8;
    }

    const int nkt = (q0 >> 6) + 2;
    for (int kt = 0; kt < nkt; kt++) {
        const int kg = kt << 6;
        __syncthreads();
        // K tile: 64 rows x 8 chunks
#pragma unroll
        for (int p = 0; p < 4; p++) {
            int idx = tid + p * 128;
            int row = idx >> 3, ck = idx & 7;
            uint4 kv = *reinterpret_cast<const uint4*>(Kb + (size_t)(kg + row) * HDIM + ck * 8);
            *reinterpret_cast<uint4*>(sm_c + 16384 + row * 128 + ((ck ^ (row & 7)) << 4)) = kv;
        }
        // V tile transposed to [d][kcol] fp16
#pragma unroll
        for (int p = 0; p < 8; p++) {
            int d4 = vd + p * 8;
            const __half* vsrc = Vb + (size_t)(kg + vk) * HDIM + d4;
            __half2 h01 = *reinterpret_cast<const __half2*>(vsrc);
            __half2 h23 = *reinterpret_cast<const __half2*>(vsrc + 2);
            *reinterpret_cast<__half*>(sm_c + 24576 + aswz16(d4 + 0, vk)) = __low2half(h01);
            *reinterpret_cast<__half*>(sm_c + 24576 + aswz16(d4 + 1, vk)) = __high2half(h01);
            *reinterpret_cast<__half*>(sm_c + 24576 + aswz16(d4 + 2, vk)) = __low2half(h23);
            *reinterpret_cast<__half*>(sm_c + 24576 + aswz16(d4 + 3, vk)) = __high2half(h23);
        }
        __syncthreads();

        // S = Q K^T (k16 blocks kb over d=64)
        float sacc[2][8][4];
#pragma unroll
        for (int mt = 0; mt < 2; mt++)
#pragma unroll
            for (int nt = 0; nt < 8; nt++)
#pragma unroll
                for (int j = 0; j < 4; j++) sacc[mt][nt][j] = 0.f;
#pragma unroll
        for (int kb = 0; kb < 4; kb++) {
            uint32_t a[2][4];
#pragma unroll
            for (int mt = 0; mt < 2; mt++)
                ldsm_x4(a[mt], sQ + abase[mt] + ((((kb << 1) + ahsel) ^ asw[mt]) << 4));
#pragma unroll
            for (int pr = 0; pr < 4; pr++) {
                uint32_t bf[4];
                ldsm_x4(bf, sK + (uint32_t)(brow_[pr] * 128)
                              + ((((kb << 1) + bhsel) ^ bsw_[pr]) << 4));
#pragma unroll
                for (int mt = 0; mt < 2; mt++) {
                    mma16(sacc[mt][pr * 2 + 0], a[mt], bf[0], bf[1]);
                    mma16(sacc[mt][pr * 2 + 1], a[mt], bf[2], bf[3]);
                }
            }
        }
        // scale + causal mask
#pragma unroll
        for (int mt = 0; mt < 2; mt++) {
            const bool need_mask = (kg + 63) > (q0 + wm + mt * 16);
#pragma unroll
            for (int nt = 0; nt < 8; nt++) {
#pragma unroll
                for (int j = 0; j < 4; j++) sacc[mt][nt][j] *= 0.125f;
                if (need_mask) {
                    int cg = kg + nt * 8 + 2 * tig;
                    if (cg     > rg[mt][0]) sacc[mt][nt][0] = -1e30f;
                    if (cg + 1 > rg[mt][0]) sacc[mt][nt][1] = -1e30f;
                    if (cg     > rg[mt][1]) sacc[mt][nt][2] = -1e30f;
                    if (cg + 1 > rg[mt][1]) sacc[mt][nt][3] = -1e30f;
                }
            }
        }

        // online softmax per m16 tile
#pragma unroll
        for (int mt = 0; mt < 2; mt++) {
            float rmax0 = -1e30f, rmax1 = -1e30f;
#pragma unroll
            for (int nt = 0; nt < 8; nt++) {
                rmax0 = fmaxf(rmax0, fmaxf(sacc[mt][nt][0], sacc[mt][nt][1]));
                rmax1 = fmaxf(rmax1, fmaxf(sacc[mt][nt][2], sacc[mt][nt][3]));
            }
            rmax0 = fmaxf(rmax0, __shfl_xor_sync(0xffffffffu, rmax0, 1));
            rmax0 = fmaxf(rmax0, __shfl_xor_sync(0xffffffffu, rmax0, 2));
            rmax1 = fmaxf(rmax1, __shfl_xor_sync(0xffffffffu, rmax1, 1));
            rmax1 = fmaxf(rmax1, __shfl_xor_sync(0xffffffffu, rmax1, 2));

            float mn0 = fmaxf(mi[mt][0], rmax0), mn1 = fmaxf(mi[mt][1], rmax1);
            float al0 = __expf(mi[mt][0] - mn0), al1 = __expf(mi[mt][1] - mn1);
            mi[mt][0] = mn0; mi[mt][1] = mn1;

            float rs0 = 0.f, rs1 = 0.f;
#pragma unroll
            for (int nt = 0; nt < 8; nt++) {
                float p0 = __expf(sacc[mt][nt][0] - mn0);
                float p1 = __expf(sacc[mt][nt][1] - mn0);
                float p2 = __expf(sacc[mt][nt][2] - mn1);
                float p3 = __expf(sacc[mt][nt][3] - mn1);
                rs0 += p0 + p1; rs1 += p2 + p3;
                int col = nt * 8 + 2 * tig;
                __half2 u01 = __floats2half2_rn(p0, p1);
                __half2 u23 = __floats2half2_rn(p2, p3);
                *reinterpret_cast<uint32_t*>(sm_c + 32768 + aswz16(wm + mt * 16 + g,     col))
                    = *reinterpret_cast<uint32_t*>(&u01);
                *reinterpret_cast<uint32_t*>(sm_c + 32768 + aswz16(wm + mt * 16 + g + 8, col))
                    = *reinterpret_cast<uint32_t*>(&u23);
            }
            rs0 += __shfl_xor_sync(0xffffffffu, rs0, 1);
            rs0 += __shfl_xor_sync(0xffffffffu, rs0, 2);
            rs1 += __shfl_xor_sync(0xffffffffu, rs1, 1);
            rs1 += __shfl_xor_sync(0xffffffffu, rs1, 2);
            li[mt][0] = li[mt][0] * al0 + rs0;
            li[mt][1] = li[mt][1] * al1 + rs1;
#pragma unroll
            for (int nt = 0; nt < 8; nt++) {
                oacc[mt][nt][0] *= al0; oacc[mt][nt][1] *= al0;
                oacc[mt][nt][2] *= al1; oacc[mt][nt][3] *= al1;
            }
        }
        __syncwarp();   // Ps rows are warp-private

        // O += P V (k16 blocks over kcol=64)
#pragma unroll
        for (int kb = 0; kb < 4; kb++) {
            uint32_t a[2][4];
#pragma unroll
            for (int mt = 0; mt < 2; mt++)
                ldsm_x4(a[mt], sP + abase[mt] + ((((kb << 1) + ahsel) ^ asw[mt]) << 4));
#pragma unroll
            for (int pr = 0; pr < 4; pr++) {
                uint32_t bf[4];
                ldsm_x4(bf, sV + (uint32_t)(brow_[pr] * 128)
                              + ((((kb << 1) + bhsel) ^ bsw_[pr]) << 4));
#pragma unroll
                for (int mt = 0; mt < 2; mt++) {
                    mma16(oacc[mt][pr * 2 + 0], a[mt], bf[0], bf[1]);
                    mma16(oacc[mt][pr * 2 + 1], a[mt], bf[2], bf[3]);
                }
            }
        }
    }

    // output: fp16 (GEMM2 gathers these bits)
#pragma unroll
    for (int mt = 0; mt < 2; mt++) {
        const float iv0 = 1.0f / li[mt][0], iv1 = 1.0f / li[mt][1];
#pragma unroll
        for (int nt = 0; nt < 8; nt++) {
            int col = nt * 8 + 2 * tig;
            __half2 w0 = __floats2half2_rn(oacc[mt][nt][0] * iv0, oacc[mt][nt][1] * iv0);
            __half2 w1 = __floats2half2_rn(oacc[mt][nt][2] * iv1, oacc[mt][nt][3] * iv1);
            *reinterpret_cast<__half2*>(O + ((size_t)bh * SEQ + rg[mt][0]) * HDIM + col) = w0;
            *reinterpret_cast<__half2*>(O + ((size_t)bh * SEQ + rg[mt][1]) * HDIM + col) = w1;
        }
    }
}

// ---------------- launcher ----------------
extern "C" void kernel_launch(void* const* d_in, const int* in_sizes, int n_in,
                              void* d_out, int out_size)
{
    const float* x     = (const float*)d_in[0];
    const float* qkv_w = (const float*)d_in[1];
    const float* qkv_b = (const float*)d_in[2];
    const float* out_w = (const float*)d_in[3];
    const float* out_b = (const float*)d_in[4];
    float* out = (float*)d_out;

    float *qkv;
    __half *q, *k, *v, *o, *xh, *qwh, *owh;
    cudaGetSymbolAddress((void**)&qkv, g_qkv);
    cudaGetSymbolAddress((void**)&q,   g_q);
    cudaGetSymbolAddress((void**)&k,   g_k);
    cudaGetSymbolAddress((void**)&v,   g_v);
    cudaGetSymbolAddress((void**)&o,   g_o);
    cudaGetSymbolAddress((void**)&xh,  g_xh);
    cudaGetSymbolAddress((void**)&qwh, g_qwh);
    cudaGetSymbolAddress((void**)&owh, g_owh);

    cudaFuncSetAttribute(gemm_fp16_pipe<false>,
                         cudaFuncAttributeMaxDynamicSharedMemorySize, GEMM_SMEM);
    cudaFuncSetAttribute(gemm_fp16_pipe<true>,
                         cudaFuncAttributeMaxDynamicSharedMemorySize, GEMM_SMEM);
    cudaFuncSetAttribute(attn_tc_kernel,
                         cudaFuncAttributeMaxDynamicSharedMemorySize, ATTN_SMEM);

    // 0) pre-convert operands to fp16
    round_fp16_kernel<<<(MROWS * DMODEL / 4 + 255) / 256, 256>>>(x, xh, MROWS * DMODEL / 4);
    round_fp16_kernel<<<(QKVN * DMODEL / 4 + 255) / 256, 256>>>(qkv_w, qwh, QKVN * DMODEL / 4);
    round_fp16_kernel<<<(DMODEL * DMODEL / 4 + 255) / 256, 256>>>(out_w, owh, DMODEL * DMODEL / 4);

    // 1) QKV projection: CTA tile 128x256, fp16 in / fp32 out
    dim3 g1(QKVN / 256, MROWS / 128);
    gemm_fp16_pipe<false><<<g1, 256, GEMM_SMEM>>>(xh, qwh, qkv_b, qkv,
                                                  MROWS, QKVN, DMODEL);

    // 2) RoPE + split (fp32 rotation, writes fp16 q/k/v)
    int nrope = MROWS * NHEADS * (HDIM / 2);
    rope_split_kernel<<<(nrope + 255) / 256, 256>>>(qkv, q, k, v);

    // 3) causal flash attention (fp16 mma.sync, 4 fat warps, 2 CTAs/SM)
    dim3 ga(SEQ / 128, BHT);
    attn_tc_kernel<<<ga, 128, ATTN_SMEM>>>(q, k, v, o);

    // 4) output projection with fused head-gather: CTA tile 128x256
    dim3 g2(DMODEL / 256, MROWS / 128);
    gemm_fp16_pipe<true><<<g2, 256, GEMM_SMEM>>>(o, owh, out_b, out,
                                                 MROWS, DMODEL, DMODEL);
}

// round 17
// speedup vs baseline: 2.9084x; 1.3247x over previous
#include <cuda_runtime.h>
#include <cuda_fp16.h>
#include <math.h>
#include <float.h>
#include <stdint.h>

#define BATCH   2
#define SEQ     2048
#define DMODEL  1024
#define NHEADS  16
#define HDIM    64
#define MROWS   (BATCH*SEQ)     // 4096
#define QKVN    (3*DMODEL)      // 3072
#define BHT     (BATCH*NHEADS)  // 32

// ---------------- scratch (device globals; no allocations allowed) ----------
static __device__ float  g_qkv[(size_t)MROWS * QKVN];            // fp32 GEMM1 out
static __device__ __half g_q  [(size_t)BHT * SEQ * HDIM];
static __device__ __half g_k  [(size_t)BHT * SEQ * HDIM];
static __device__ __half g_v  [(size_t)BHT * SEQ * HDIM];
static __device__ __half g_o  [(size_t)BHT * SEQ * HDIM];
static __device__ __half g_xh [(size_t)MROWS * DMODEL];          // fp16 x
static __device__ __half g_qwh[(size_t)QKVN * DMODEL];           // fp16 qkv_w
static __device__ __half g_owh[(size_t)DMODEL * DMODEL];         // fp16 out_w

// ---------------- helpers ----------------
__device__ __forceinline__ uint32_t smem_u32(const void* p) {
    uint32_t a;
    asm("{ .reg .u64 t; cvta.to.shared.u64 t, %1; cvt.u32.u64 %0, t; }" : "=r"(a) : "l"(p));
    return a;
}

__device__ __forceinline__ void cp_async16(uint32_t dst, const void* src) {
    asm volatile("cp.async.ca.shared.global [%0], [%1], 16;" :: "r"(dst), "l"(src) : "memory");
}
#define CP_COMMIT() asm volatile("cp.async.commit_group;" ::: "memory")
#define CP_WAIT(n)  asm volatile("cp.async.wait_group %0;" :: "n"(n) : "memory")

// ldmatrix x4: 4 8x8-b16 matrices -> 4 regs/lane
__device__ __forceinline__ void ldsm_x4(uint32_t* r, uint32_t addr) {
    asm volatile("ldmatrix.sync.aligned.m8n8.x4.shared.b16 {%0,%1,%2,%3}, [%4];"
        : "=r"(r[0]), "=r"(r[1]), "=r"(r[2]), "=r"(r[3]) : "r"(addr));
}
// transposed variant: fragment = matrix^T (used for V in PV)
__device__ __forceinline__ void ldsm_x4_trans(uint32_t* r, uint32_t addr) {
    asm volatile("ldmatrix.sync.aligned.m8n8.x4.trans.shared.b16 {%0,%1,%2,%3}, [%4];"
        : "=r"(r[0]), "=r"(r[1]), "=r"(r[2]), "=r"(r[3]) : "r"(addr));
}

// D = A(16x8) * B(8x8)^T + D over k16, fp16 in / fp32 accumulate
__device__ __forceinline__ void mma16(float* d, const uint32_t* a, uint32_t b0, uint32_t b1) {
    asm volatile(
        "mma.sync.aligned.m16n8k16.row.col.f32.f16.f16.f32 "
        "{%0,%1,%2,%3}, {%4,%5,%6,%7}, {%8,%9}, {%0,%1,%2,%3};"
        : "+f"(d[0]), "+f"(d[1]), "+f"(d[2]), "+f"(d[3])
        : "r"(a[0]), "r"(a[1]), "r"(a[2]), "r"(a[3]), "r"(b0), "r"(b1));
}

// ---------------- fp16 pre-conversion pass ----------------
__global__ void round_fp16_kernel(const float* __restrict__ in,
                                  __half* __restrict__ out, int n4)
{
    int i = blockIdx.x * blockDim.x + threadIdx.x;
    if (i >= n4) return;
    float4 v = reinterpret_cast<const float4*>(in)[i];
    __half2 h0 = __floats2half2_rn(v.x, v.y);
    __half2 h1 = __floats2half2_rn(v.z, v.w);
    uint2 u;
    u.x = *reinterpret_cast<uint32_t*>(&h0);
    u.y = *reinterpret_cast<uint32_t*>(&h1);
    reinterpret_cast<uint2*>(out)[i] = u;
}

// ============ FP16 mma.sync GEMM (R16 verbatim — proven) ====================
#define STAGES   4
#define A_STG_B  8192
#define B_STG_B  16384
#define GEMM_SMEM (STAGES * (A_STG_B + B_STG_B))   // 98304

template<bool GATHER>
__global__ __launch_bounds__(256)
void gemm_fp16_pipe(const __half* __restrict__ A, const __half* __restrict__ B,
                    const float* __restrict__ bias, float* __restrict__ C,
                    int M, int N, int K)
{
    extern __shared__ float sm_f[];
    const uint32_t sbase = smem_u32(sm_f);
    const int tid  = threadIdx.x;
    const int warp = tid >> 5, lane = tid & 31;
    const int g    = lane >> 2, tig = lane & 3;
    const int wm   = (warp >> 2) * 64;
    const int wn   = (warp & 3) * 64;
    const int bm   = blockIdx.y * 128;
    const int bn   = blockIdx.x * 256;

    const int prow = tid >> 1;
    const int pc0  = tid & 1;
    const int psw  = (prow >> 1) & 3;
    const uint32_t pd0 = (uint32_t)(prow * 64 + (( pc0      ^ psw) << 4));
    const uint32_t pd1 = (uint32_t)(prow * 64 + (((pc0 + 2) ^ psw) << 4));

    auto a_src = [&](int row, int kcol) -> const __half* {
        if (!GATHER) {
            return A + (size_t)(bm + row) * K + kcol;
        } else {
            int m = bm + row;
            int b = m >> 11, s = m & 2047;
            int h = kcol >> 6, hd = kcol & 63;
            return A + ((((size_t)(b * NHEADS + h) << 11) + s) << 6) + hd;
        }
    };

    auto issue = [&](int ch) {
        const int st = ch & (STAGES - 1);
        const int k0 = ch << 5;
        const uint32_t ab = sbase + st * A_STG_B;
        const uint32_t bb = sbase + STAGES * A_STG_B + st * B_STG_B;
        cp_async16(ab + pd0, a_src(prow, k0 + pc0 * 8));
        cp_async16(ab + pd1, a_src(prow, k0 + (pc0 + 2) * 8));
        const __half* br0 = B + (size_t)(bn + prow) * K + k0;
        const __half* br1 = B + (size_t)(bn + prow + 128) * K + k0;
        cp_async16(bb + pd0, br0 + pc0 * 8);
        cp_async16(bb + pd1, br0 + (pc0 + 2) * 8);
        cp_async16(bb + 128 * 64 + pd0, br1 + pc0 * 8);
        cp_async16(bb + 128 * 64 + pd1, br1 + (pc0 + 2) * 8);
        CP_COMMIT();
    };

    uint32_t offA[4][2];
#pragma unroll
    for (int mt = 0; mt < 4; mt++) {
        int rowA = wm + mt * 16 + (lane & 15);
        int sw = (rowA >> 1) & 3;
#pragma unroll
        for (int h = 0; h < 2; h++) {
            int ck = h * 2 + (lane >> 4);
            offA[mt][h] = (uint32_t)(rowA * 64 + ((ck ^ sw) << 4));
        }
    }
    uint32_t offB[4][2];
#pragma unroll
    for (int pr = 0; pr < 4; pr++) {
        int rowB = wn + pr * 16 + ((lane >> 4) << 3) + (lane & 7);
        int sw = (rowB >> 1) & 3;
#pragma unroll
        for (int h = 0; h < 2; h++) {
            int ck = h * 2 + ((lane >> 3) & 1);
            offB[pr][h] = (uint32_t)(rowB * 64 + ((ck ^ sw) << 4));
        }
    }

    float acc[4][8][4];
#pragma unroll
    for (int mt = 0; mt < 4; mt++)
#pragma unroll
        for (int nt = 0; nt < 8; nt++)
#pragma unroll
            for (int j = 0; j < 4; j++) acc[mt][nt][j] = 0.f;

    const int nch = K >> 5;
    issue(0); issue(1); issue(2);

    for (int ch = 0; ch < nch; ch++) {
        CP_WAIT(2);
        __syncthreads();
        const uint32_t aS = sbase + (ch & (STAGES - 1)) * A_STG_B;
        const uint32_t bS = sbase + STAGES * A_STG_B + (ch & (STAGES - 1)) * B_STG_B;

#pragma unroll
        for (int h = 0; h < 2; h++) {
            uint32_t af[4][4], bf[4][4];
#pragma unroll
            for (int mt = 0; mt < 4; mt++) ldsm_x4(af[mt], aS + offA[mt][h]);
#pragma unroll
            for (int pr = 0; pr < 4; pr++) ldsm_x4(bf[pr], bS + offB[pr][h]);
#pragma unroll
            for (int pr = 0; pr < 4; pr++)
#pragma unroll
                for (int sub = 0; sub < 2; sub++) {
                    const int nt = pr * 2 + sub;
#pragma unroll
                    for (int mt = 0; mt < 4; mt++)
                        mma16(acc[mt][nt], af[mt], bf[pr][sub * 2], bf[pr][sub * 2 + 1]);
                }
        }
        if (ch + 3 < nch) issue(ch + 3);
    }

#pragma unroll
    for (int nt = 0; nt < 8; nt++) {
        int cc = bn + wn + nt * 8 + 2 * tig;
        float bv0 = bias[cc], bv1 = bias[cc + 1];
#pragma unroll
        for (int mt = 0; mt < 4; mt++) {
            int rr = bm + wm + mt * 16 + g;
            float2 v0, v1;
            v0.x = acc[mt][nt][0] + bv0; v0.y = acc[mt][nt][1] + bv1;
            v1.x = acc[mt][nt][2] + bv0; v1.y = acc[mt][nt][3] + bv1;
            *reinterpret_cast<float2*>(C + (size_t)rr * N + cc)       = v0;
            *reinterpret_cast<float2*>(C + (size_t)(rr + 8) * N + cc) = v1;
        }
    }
}

// ---------------- RoPE + split -> fp16 q/k/v [B,H,S,Hd] ---------------------
__global__ void rope_split_kernel(const float* __restrict__ qkv,
                                  __half* __restrict__ q, __half* __restrict__ k,
                                  __half* __restrict__ v)
{
    int idx = blockIdx.x * blockDim.x + threadIdx.x;
    if (idx >= MROWS * NHEADS * (HDIM / 2)) return;
    int j = idx & 31;
    int h = (idx >> 5) & 15;
    int m = idx >> 9;
    int b = m >> 11;
    int s = m & 2047;

    float inv_freq = 1.0f / powf(10000.0f, (float)j * (1.0f / 32.0f));
    float ang = (float)s * inv_freq;
    float sn, c;
    sincosf(ang, &sn, &c);

    size_t ib = (size_t)m * QKVN + (size_t)h * HDIM;
    size_t ob = ((size_t)(b * NHEADS + h) * SEQ + s) * HDIM;

    float q1 = qkv[ib + j],          q2 = qkv[ib + 32 + j];
    q[ob + j]      = __float2half_rn(q1 * c  - q2 * sn);
    q[ob + 32 + j] = __float2half_rn(q1 * sn + q2 * c);

    float k1 = qkv[ib + DMODEL + j], k2 = qkv[ib + DMODEL + 32 + j];
    k[ob + j]      = __float2half_rn(k1 * c  - k2 * sn);
    k[ob + 32 + j] = __float2half_rn(k1 * sn + k2 * c);

    v[ob + j]      = __float2half_rn(qkv[ib + 2 * DMODEL + j]);
    v[ob + 32 + j] = __float2half_rn(qkv[ib + 2 * DMODEL + 32 + j]);
}

// ============ FP16 flash attention: V-trans ldmatrix + async double-buffer ==
// BQ=128, BK=64, 128 threads = 4 warps, warp owns 32 q-rows.
// K AND V both stored row-major [kcol][d] (identical fills, pure 16B copies);
// PV B-fragments come from ldmatrix.x4.trans on V (no transpose buffer).
// K/V double-buffered; iteration kt prefetches kt+1 via cp.async.
// SMEM rows = 64 fp16 (128B, 8 chunks); chunk c ^ (row&7).
// Layout (bytes): Qs@0 (16K), K0@16384 K1@24576, V0@32768 V1@40960, Ps@49152 (16K)
#define ATTN_SMEM 65536
__device__ __forceinline__ uint32_t aswz16(int row, int col) {  // col in fp16
    return (uint32_t)(row * 128 + ((((col >> 3) ^ (row & 7))) << 4) + ((col & 7) << 1));
}

__global__ __launch_bounds__(128, 2)
void attn_tc_kernel(const __half* __restrict__ Q, const __half* __restrict__ K,
                    const __half* __restrict__ V, __half* __restrict__ O)
{
    extern __shared__ char sm_c[];
    const uint32_t sb = smem_u32(sm_c);
    const uint32_t sQ = sb, sP = sb + 49152;

    const int tid  = threadIdx.x;
    const int warp = tid >> 5, lane = tid & 31;
    const int g    = lane >> 2, tig = lane & 3;
    const int wm   = warp * 32;
    const int bh   = blockIdx.y;
    const int qi   = gridDim.x - 1 - blockIdx.x;   // heavy blocks first
    const int q0   = qi * 128;

    const __half* Qb = Q + (size_t)bh * SEQ * HDIM;
    const __half* Kb = K + (size_t)bh * SEQ * HDIM;
    const __half* Vb = V + (size_t)bh * SEQ * HDIM;

    // Q tile via cp.async: 128 rows x 8 chunks
#pragma unroll
    for (int p = 0; p < 8; p++) {
        int idx = tid + p * 128;
        int row = idx >> 3, ck = idx & 7;
        cp_async16(sQ + row * 128 + ((ck ^ (row & 7)) << 4),
                   Qb + (size_t)(q0 + row) * HDIM + ck * 8);
    }
    CP_COMMIT();

    const int nkt = (q0 >> 6) + 2;

    // K/V fill for iteration kt2 into buffer kt2&1 (pure copies, same layout)
    auto fill_kv = [&](int kt2) {
        const int kg2 = kt2 << 6;
        const uint32_t kbuf = sb + 16384 + (uint32_t)(kt2 & 1) * 8192;
        const uint32_t vbuf = sb + 32768 + (uint32_t)(kt2 & 1) * 8192;
#pragma unroll
        for (int p = 0; p < 4; p++) {
            int idx = tid + p * 128;
            int row = idx >> 3, ck = idx & 7;
            uint32_t off = (uint32_t)(row * 128 + ((ck ^ (row & 7)) << 4));
            const __half* src = Kb + (size_t)(kg2 + row) * HDIM + ck * 8;
            cp_async16(kbuf + off, src);
            cp_async16(vbuf + off, Vb + (size_t)(kg2 + row) * HDIM + ck * 8);
        }
        CP_COMMIT();
    };
    fill_kv(0);

    // A-side (Q/P) fragment pieces per m16 tile
    uint32_t abase[2]; int asw[2];
#pragma unroll
    for (int mt = 0; mt < 2; mt++) {
        int rowA = wm + mt * 16 + (lane & 15);
        abase[mt] = (uint32_t)(rowA * 128);
        asw[mt]   = rowA & 7;
    }
    const int ahsel = lane >> 4;
    // K fragments (non-trans): rows = kcol
    int brow_[4], bsw_[4];
#pragma unroll
    for (int pr = 0; pr < 4; pr++) {
        brow_[pr] = pr * 16 + ((lane >> 4) << 3) + (lane & 7);
        bsw_[pr]  = brow_[pr] & 7;
    }
    const int bhsel = (lane >> 3) & 1;
    // V fragments (trans): per-kb row = kb*16 + vroff, d-chunk = pr*2 + (lane>>4)
    const int vroff = ((lane >> 3) & 1) * 8 + (lane & 7);
    uint32_t voff[4];
#pragma unroll
    for (int pr = 0; pr < 4; pr++) {
        int chunk = pr * 2 + (lane >> 4);
        voff[pr] = (uint32_t)(vroff * 128 + ((chunk ^ (vroff & 7)) << 4));
    }

    float oacc[2][8][4];
#pragma unroll
    for (int mt = 0; mt < 2; mt++)
#pragma unroll
        for (int nt = 0; nt < 8; nt++)
#pragma unroll
            for (int j = 0; j < 4; j++) oacc[mt][nt][j] = 0.f;
    float mi[2][2], li[2][2];
#pragma unroll
    for (int mt = 0; mt < 2; mt++) {
        mi[mt][0] = mi[mt][1] = -1e30f;
        li[mt][0] = li[mt][1] = 0.f;
    }
    int rg[2][2];
#pragma unroll
    for (int mt = 0; mt < 2; mt++) {
        rg[mt][0] = q0 + wm + mt * 16 + g;
        rg[mt][1] = rg[mt][0] + 8;
    }

    for (int kt = 0; kt < nkt; kt++) {
        const int kg = kt << 6;
        const uint32_t sK = sb + 16384 + (uint32_t)(kt & 1) * 8192;
        const uint32_t sV = sb + 32768 + (uint32_t)(kt & 1) * 8192;
        CP_WAIT(0);          // this iteration's K/V (and Q on kt=0) complete
        __syncthreads();     // fills visible to all; prev-iter readers done
        if (kt + 1 < nkt) fill_kv(kt + 1);   // prefetch into other buffer

        // S = Q K^T
        float sacc[2][8][4];
#pragma unroll
        for (int mt = 0; mt < 2; mt++)
#pragma unroll
            for (int nt = 0; nt < 8; nt++)
#pragma unroll
                for (int j = 0; j < 4; j++) sacc[mt][nt][j] = 0.f;
#pragma unroll
        for (int kb = 0; kb < 4; kb++) {
            uint32_t a[2][4];
#pragma unroll
            for (int mt = 0; mt < 2; mt++)
                ldsm_x4(a[mt], sQ + abase[mt] + ((((kb << 1) + ahsel) ^ asw[mt]) << 4));
#pragma unroll
            for (int pr = 0; pr < 4; pr++) {
                uint32_t bf[4];
                ldsm_x4(bf, sK + (uint32_t)(brow_[pr] * 128)
                              + ((((kb << 1) + bhsel) ^ bsw_[pr]) << 4));
#pragma unroll
                for (int mt = 0; mt < 2; mt++) {
                    mma16(sacc[mt][pr * 2 + 0], a[mt], bf[0], bf[1]);
                    mma16(sacc[mt][pr * 2 + 1], a[mt], bf[2], bf[3]);
                }
            }
        }
        // scale + causal mask
#pragma unroll
        for (int mt = 0; mt < 2; mt++) {
            const bool need_mask = (kg + 63) > (q0 + wm + mt * 16);
#pragma unroll
            for (int nt = 0; nt < 8; nt++) {
#pragma unroll
                for (int j = 0; j < 4; j++) sacc[mt][nt][j] *= 0.125f;
                if (need_mask) {
                    int cg = kg + nt * 8 + 2 * tig;
                    if (cg     > rg[mt][0]) sacc[mt][nt][0] = -1e30f;
                    if (cg + 1 > rg[mt][0]) sacc[mt][nt][1] = -1e30f;
                    if (cg     > rg[mt][1]) sacc[mt][nt][2] = -1e30f;
                    if (cg + 1 > rg[mt][1]) sacc[mt][nt][3] = -1e30f;
                }
            }
        }

        // online softmax per m16 tile
#pragma unroll
        for (int mt = 0; mt < 2; mt++) {
            float rmax0 = -1e30f, rmax1 = -1e30f;
#pragma unroll
            for (int nt = 0; nt < 8; nt++) {
                rmax0 = fmaxf(rmax0, fmaxf(sacc[mt][nt][0], sacc[mt][nt][1]));
                rmax1 = fmaxf(rmax1, fmaxf(sacc[mt][nt][2], sacc[mt][nt][3]));
            }
            rmax0 = fmaxf(rmax0, __shfl_xor_sync(0xffffffffu, rmax0, 1));
            rmax0 = fmaxf(rmax0, __shfl_xor_sync(0xffffffffu, rmax0, 2));
            rmax1 = fmaxf(rmax1, __shfl_xor_sync(0xffffffffu, rmax1, 1));
            rmax1 = fmaxf(rmax1, __shfl_xor_sync(0xffffffffu, rmax1, 2));

            float mn0 = fmaxf(mi[mt][0], rmax0), mn1 = fmaxf(mi[mt][1], rmax1);
            float al0 = __expf(mi[mt][0] - mn0), al1 = __expf(mi[mt][1] - mn1);
            mi[mt][0] = mn0; mi[mt][1] = mn1;

            float rs0 = 0.f, rs1 = 0.f;
#pragma unroll
            for (int nt = 0; nt < 8; nt++) {
                float p0 = __expf(sacc[mt][nt][0] - mn0);
                float p1 = __expf(sacc[mt][nt][1] - mn0);
                float p2 = __expf(sacc[mt][nt][2] - mn1);
                float p3 = __expf(sacc[mt][nt][3] - mn1);
                rs0 += p0 + p1; rs1 += p2 + p3;
                int col = nt * 8 + 2 * tig;
                __half2 u01 = __floats2half2_rn(p0, p1);
                __half2 u23 = __floats2half2_rn(p2, p3);
                *reinterpret_cast<uint32_t*>(sm_c + 49152 + aswz16(wm + mt * 16 + g,     col))
                    = *reinterpret_cast<uint32_t*>(&u01);
                *reinterpret_cast<uint32_t*>(sm_c + 49152 + aswz16(wm + mt * 16 + g + 8, col))
                    = *reinterpret_cast<uint32_t*>(&u23);
            }
            rs0 += __shfl_xor_sync(0xffffffffu, rs0, 1);
            rs0 += __shfl_xor_sync(0xffffffffu, rs0, 2);
            rs1 += __shfl_xor_sync(0xffffffffu, rs1, 1);
            rs1 += __shfl_xor_sync(0xffffffffu, rs1, 2);
            li[mt][0] = li[mt][0] * al0 + rs0;
            li[mt][1] = li[mt][1] * al1 + rs1;
#pragma unroll
            for (int nt = 0; nt < 8; nt++) {
                oacc[mt][nt][0] *= al0; oacc[mt][nt][1] *= al0;
                oacc[mt][nt][2] *= al1; oacc[mt][nt][3] *= al1;
            }
        }
        __syncwarp();   // Ps rows are warp-private

        // O += P V   (V fragments via ldmatrix.trans on row-major V tile)
#pragma unroll
        for (int kb = 0; kb < 4; kb++) {
            uint32_t a[2][4];
#pragma unroll
            for (int mt = 0; mt < 2; mt++)
                ldsm_x4(a[mt], sP + abase[mt] + ((((kb << 1) + ahsel) ^ asw[mt]) << 4));
#pragma unroll
            for (int pr = 0; pr < 4; pr++) {
                uint32_t bf[4];
                ldsm_x4_trans(bf, sV + (uint32_t)(kb * 2048) + voff[pr]);
#pragma unroll
                for (int mt = 0; mt < 2; mt++) {
                    mma16(oacc[mt][pr * 2 + 0], a[mt], bf[0], bf[1]);
                    mma16(oacc[mt][pr * 2 + 1], a[mt], bf[2], bf[3]);
                }
            }
        }
    }

    // output: fp16 (GEMM2 gathers these bits)
#pragma unroll
    for (int mt = 0; mt < 2; mt++) {
        const float iv0 = 1.0f / li[mt][0], iv1 = 1.0f / li[mt][1];
#pragma unroll
        for (int nt = 0; nt < 8; nt++) {
            int col = nt * 8 + 2 * tig;
            __half2 w0 = __floats2half2_rn(oacc[mt][nt][0] * iv0, oacc[mt][nt][1] * iv0);
            __half2 w1 = __floats2half2_rn(oacc[mt][nt][2] * iv1, oacc[mt][nt][3] * iv1);
            *reinterpret_cast<__half2*>(O + ((size_t)bh * SEQ + rg[mt][0]) * HDIM + col) = w0;
            *reinterpret_cast<__half2*>(O + ((size_t)bh * SEQ + rg[mt][1]) * HDIM + col) = w1;
        }
    }
}

// ---------------- launcher ----------------
extern "C" void kernel_launch(void* const* d_in, const int* in_sizes, int n_in,
                              void* d_out, int out_size)
{
    const float* x     = (const float*)d_in[0];
    const float* qkv_w = (const float*)d_in[1];
    const float* qkv_b = (const float*)d_in[2];
    const float* out_w = (const float*)d_in[3];
    const float* out_b = (const float*)d_in[4];
    float* out = (float*)d_out;

    float *qkv;
    __half *q, *k, *v, *o, *xh, *qwh, *owh;
    cudaGetSymbolAddress((void**)&qkv, g_qkv);
    cudaGetSymbolAddress((void**)&q,   g_q);
    cudaGetSymbolAddress((void**)&k,   g_k);
    cudaGetSymbolAddress((void**)&v,   g_v);
    cudaGetSymbolAddress((void**)&o,   g_o);
    cudaGetSymbolAddress((void**)&xh,  g_xh);
    cudaGetSymbolAddress((void**)&qwh, g_qwh);
    cudaGetSymbolAddress((void**)&owh, g_owh);

    cudaFuncSetAttribute(gemm_fp16_pipe<false>,
                         cudaFuncAttributeMaxDynamicSharedMemorySize, GEMM_SMEM);
    cudaFuncSetAttribute(gemm_fp16_pipe<true>,
                         cudaFuncAttributeMaxDynamicSharedMemorySize, GEMM_SMEM);
    cudaFuncSetAttribute(attn_tc_kernel,
                         cudaFuncAttributeMaxDynamicSharedMemorySize, ATTN_SMEM);

    // 0) pre-convert operands to fp16
    round_fp16_kernel<<<(MROWS * DMODEL / 4 + 255) / 256, 256>>>(x, xh, MROWS * DMODEL / 4);
    round_fp16_kernel<<<(QKVN * DMODEL / 4 + 255) / 256, 256>>>(qkv_w, qwh, QKVN * DMODEL / 4);
    round_fp16_kernel<<<(DMODEL * DMODEL / 4 + 255) / 256, 256>>>(out_w, owh, DMODEL * DMODEL / 4);

    // 1) QKV projection: CTA tile 128x256, fp16 in / fp32 out
    dim3 g1(QKVN / 256, MROWS / 128);
    gemm_fp16_pipe<false><<<g1, 256, GEMM_SMEM>>>(xh, qwh, qkv_b, qkv,
                                                  MROWS, QKVN, DMODEL);

    // 2) RoPE + split (fp32 rotation, writes fp16 q/k/v)
    int nrope = MROWS * NHEADS * (HDIM / 2);
    rope_split_kernel<<<(nrope + 255) / 256, 256>>>(qkv, q, k, v);

    // 3) causal flash attention (V-trans ldmatrix + double-buffered cp.async)
    dim3 ga(SEQ / 128, BHT);
    attn_tc_kernel<<<ga, 128, ATTN_SMEM>>>(q, k, v, o);

    // 4) output projection with fused head-gather: CTA tile 128x256
    dim3 g2(DMODEL / 256, MROWS / 128);
    gemm_fp16_pipe<true><<<g2, 256, GEMM_SMEM>>>(o, owh, out_b, out,
                                                 MROWS, DMODEL, DMODEL);
}